// round 12
// baseline (speedup 1.0000x reference)
#include <cuda_runtime.h>
#include <cuda_bf16.h>
#include <math.h>

// Problem constants
#define BB 4
#define TT 2048
#define CC 1024
#define HH 8
#define DD 128
#define NTOK (BB*TT)          // 8192
#define BH   (BB*HH)          // 32
#define WPL  ((size_t)CC*CC)  // weight plane elems

// ---------------------------------------------------------------------------
// Scratch
// ---------------------------------------------------------------------------
#define SZ_F32 ((size_t)NTOK*CC*4)
#define SZ_BF  ((size_t)NTOK*CC*2)
#define SZ_WPL ((size_t)4*CC*CC*2)
#define SZ_P   ((size_t)BH*TT*4)

#define OFF_XNH ((size_t)0)
#define OFF_XNL (OFF_XNH + SZ_BF)
#define OFF_WH  (OFF_XNL + SZ_BF)
#define OFF_WL  (OFF_WH + SZ_WPL)
#define OFF_QF  (OFF_WL + SZ_WPL)
#define OFF_KF  (OFF_QF + SZ_F32)
#define OFF_QH  (OFF_KF + SZ_F32)
#define OFF_QL  (OFF_QH + SZ_BF)
#define OFF_KH  (OFF_QL + SZ_BF)
#define OFF_KL  (OFF_KH + SZ_BF)
#define OFF_VTH (OFF_KL + SZ_BF)
#define OFF_VTL (OFF_VTH + SZ_BF)
#define OFF_AOH (OFF_VTL + SZ_BF)
#define OFF_AOL (OFF_AOH + SZ_BF)
#define OFF_QP  (OFF_AOL + SZ_BF)
#define OFF_KP  (OFF_QP + SZ_P)
#define SCRATCH_BYTES (OFF_KP + SZ_P)

__device__ __align__(256) unsigned char g_scratch[SCRATCH_BYTES];

// ---------------------------------------------------------------------------
// helpers
// ---------------------------------------------------------------------------
__device__ __forceinline__ void mma_bf16(float* c, const unsigned* a,
                                         unsigned b0, unsigned b1) {
    asm volatile(
        "mma.sync.aligned.m16n8k16.row.col.f32.bf16.bf16.f32 "
        "{%0,%1,%2,%3},{%4,%5,%6,%7},{%8,%9},{%0,%1,%2,%3};"
        : "+f"(c[0]), "+f"(c[1]), "+f"(c[2]), "+f"(c[3])
        : "r"(a[0]), "r"(a[1]), "r"(a[2]), "r"(a[3]), "r"(b0), "r"(b1));
}

__device__ __forceinline__ void ldsm_x4(unsigned r[4], unsigned addr) {
    asm volatile("ldmatrix.sync.aligned.m8n8.x4.shared.b16 {%0,%1,%2,%3}, [%4];"
        : "=r"(r[0]), "=r"(r[1]), "=r"(r[2]), "=r"(r[3]) : "r"(addr));
}

#define CP16(dst, src) \
    asm volatile("cp.async.cg.shared.global [%0], [%1], 16;" :: "r"(dst), "l"(src))
#define CP4(dst, src) \
    asm volatile("cp.async.ca.shared.global [%0], [%1], 4;" :: "r"(dst), "l"(src))
#define CP_COMMIT() asm volatile("cp.async.commit_group;")
#define CP_WAIT0()  asm volatile("cp.async.wait_group 0;")
#define CP_WAIT1()  asm volatile("cp.async.wait_group 1;")

__device__ __forceinline__ void split2(float a, float b, unsigned& hi, unsigned& lo) {
    __nv_bfloat162 h = __floats2bfloat162_rn(a, b);
    float la = a - __bfloat162float(h.x);
    float lb = b - __bfloat162float(h.y);
    __nv_bfloat162 l = __floats2bfloat162_rn(la, lb);
    hi = *(unsigned*)&h;
    lo = *(unsigned*)&l;
}

// ---------------------------------------------------------------------------
// LayerNorm -> bf16 hi/lo planes
// ---------------------------------------------------------------------------
__global__ __launch_bounds__(256) void ln_split(
    const float* __restrict__ x, const float* __restrict__ gam,
    const float* __restrict__ bet,
    __nv_bfloat16* __restrict__ xnh, __nv_bfloat16* __restrict__ xnl)
{
    int row = blockIdx.x;
    int t   = threadIdx.x;
    const float4* xr = (const float4*)(x + (size_t)row * CC);
    float4 v = xr[t];
    float s  = v.x + v.y + v.z + v.w;
    float ss = v.x*v.x + v.y*v.y + v.z*v.z + v.w*v.w;
    #pragma unroll
    for (int o = 16; o; o >>= 1) {
        s  += __shfl_xor_sync(0xffffffffu, s,  o);
        ss += __shfl_xor_sync(0xffffffffu, ss, o);
    }
    __shared__ float ws[8], wss[8];
    int wid = t >> 5;
    if ((t & 31) == 0) { ws[wid] = s; wss[wid] = ss; }
    __syncthreads();
    s = 0.f; ss = 0.f;
    #pragma unroll
    for (int i = 0; i < 8; i++) { s += ws[i]; ss += wss[i]; }
    float mu  = s * (1.f / CC);
    float var = ss * (1.f / CC) - mu * mu;
    float inv = rsqrtf(var + 1e-5f);
    float4 g4 = ((const float4*)gam)[t];
    float4 b4 = ((const float4*)bet)[t];
    float4 o;
    o.x = (v.x - mu) * inv * g4.x + b4.x;
    o.y = (v.y - mu) * inv * g4.y + b4.y;
    o.z = (v.z - mu) * inv * g4.z + b4.z;
    o.w = (v.w - mu) * inv * g4.w + b4.w;
    unsigned h0, l0, h1, l1;
    split2(o.x, o.y, h0, l0);
    split2(o.z, o.w, h1, l1);
    size_t off = (size_t)row * CC + t*4;
    *(uint2*)&xnh[off] = make_uint2(h0, h1);
    *(uint2*)&xnl[off] = make_uint2(l0, l1);
}

// ---------------------------------------------------------------------------
// Split 4 weight matrices into bf16 hi/lo planes: plane order Wq,Wk,Wv,Wo
// ---------------------------------------------------------------------------
__global__ __launch_bounds__(256) void wsplit(
    const float* __restrict__ w0, const float* __restrict__ w1,
    const float* __restrict__ w2, const float* __restrict__ w3,
    __nv_bfloat16* __restrict__ wh, __nv_bfloat16* __restrict__ wl)
{
    int mid = blockIdx.x >> 10;
    const float* src = (mid == 0) ? w0 : (mid == 1) ? w1 : (mid == 2) ? w2 : w3;
    size_t idx = ((size_t)(blockIdx.x & 1023))*1024 + threadIdx.x*4;
    float4 v = *(const float4*)(src + idx);
    unsigned h0, l0, h1, l1;
    split2(v.x, v.y, h0, l0);
    split2(v.z, v.w, h1, l1);
    size_t off = (size_t)mid*WPL + idx;
    *(uint2*)&wh[off] = make_uint2(h0, h1);
    *(uint2*)&wl[off] = make_uint2(l0, l1);
}

// ---------------------------------------------------------------------------
// 3xBF16 GEMM: cp.async double buffer + ldmatrix, 128x128x32, 2 CTA/SM.
// Term-major MMA ordering: same-accumulator reuse distance = 8 MMAs.
// MODE 0: QKV fused (grid.x=24; sel = x>>3): sel 0/1 -> fp32 head-major
//         q/k buffers; sel 2 -> transposed bf16 hi/lo planes [B,H,D,T]
// MODE 1: out0 = X + acc (fp32 row-major)
// ---------------------------------------------------------------------------
#define GSTR 40
#define GEMM_SMEM (4*2*128*GSTR*2)   // 81920 B

template<int MODE>
__global__ __launch_bounds__(256, 2) void gemm2(
    const __nv_bfloat16* __restrict__ Ah, const __nv_bfloat16* __restrict__ Al,
    const __nv_bfloat16* __restrict__ Wh, const __nv_bfloat16* __restrict__ Wl,
    const float* __restrict__ X,
    float* __restrict__ out0, float* __restrict__ out1,
    __nv_bfloat16* __restrict__ oh, __nv_bfloat16* __restrict__ ol)
{
    extern __shared__ __nv_bfloat16 smb[];
    __nv_bfloat16* sAh = smb;
    __nv_bfloat16* sAl = sAh + 2*128*GSTR;
    __nv_bfloat16* sBh = sAl + 2*128*GSTR;
    __nv_bfloat16* sBl = sBh + 2*128*GSTR;
    unsigned uAh = (unsigned)__cvta_generic_to_shared(sAh);
    unsigned uAl = (unsigned)__cvta_generic_to_shared(sAl);
    unsigned uBh = (unsigned)__cvta_generic_to_shared(sBh);
    unsigned uBl = (unsigned)__cvta_generic_to_shared(sBl);

    int tid = threadIdx.x, lane = tid & 31, warp = tid >> 5;
    int g = lane >> 2, tig = lane & 3;
    int wm = warp >> 1, wn = warp & 1;
    int sel = (MODE == 0) ? (blockIdx.x >> 3) : 0;
    int n0 = (MODE == 0) ? ((blockIdx.x & 7) << 7) : (blockIdx.x << 7);
    int m0 = blockIdx.y << 7;
    const __nv_bfloat16* Wph = Wh + (size_t)sel*WPL;
    const __nv_bfloat16* Wpl = Wl + (size_t)sel*WPL;

    int lr = tid >> 2;
    int lc8 = (tid & 3) * 8;

    float acc[16][4];
    #pragma unroll
    for (int i = 0; i < 16; i++)
        #pragma unroll
        for (int j = 0; j < 4; j++) acc[i][j] = 0.f;

    auto load_stage = [&](int buf, int k0) {
        size_t a0 = (size_t)(m0 + lr) * CC + k0 + lc8;
        size_t b0 = (size_t)(n0 + lr) * CC + k0 + lc8;
        unsigned d0 = (unsigned)(((buf*128 + lr)*GSTR + lc8) * 2);
        unsigned d1 = (unsigned)(((buf*128 + lr + 64)*GSTR + lc8) * 2);
        CP16(uAh + d0, Ah + a0);  CP16(uAh + d1, Ah + a0 + (size_t)64*CC);
        CP16(uAl + d0, Al + a0);  CP16(uAl + d1, Al + a0 + (size_t)64*CC);
        CP16(uBh + d0, Wph + b0); CP16(uBh + d1, Wph + b0 + (size_t)64*CC);
        CP16(uBl + d0, Wpl + b0); CP16(uBl + d1, Wpl + b0 + (size_t)64*CC);
    };

    load_stage(0, 0);
    CP_COMMIT();
    CP_WAIT0();
    __syncthreads();

    int lra = ((lane >> 3) & 1) * 8 + (lane & 7);
    int lca = (lane >> 4) * 8;
    const int NIT = CC / 32;

    for (int it = 0; it < NIT; it++) {
        int buf = it & 1;
        if (it + 1 < NIT) { load_stage(buf ^ 1, (it + 1) * 32); CP_COMMIT(); }

        int sb = buf * 128;
        #pragma unroll
        for (int kk = 0; kk < 2; kk++) {
            int col = kk*16 + lca;
            unsigned ah[2][4], al2[2][4];
            #pragma unroll
            for (int mi = 0; mi < 2; mi++) {
                unsigned offA = (unsigned)(((sb + wm*32 + mi*16 + lra)*GSTR + col) * 2);
                ldsm_x4(ah[mi],  uAh + offA);
                ldsm_x4(al2[mi], uAl + offA);
            }
            // process ng in pairs; term-major so same-acc reuse distance = 8
            #pragma unroll
            for (int np = 0; np < 2; np++) {
                unsigned b4h[2][4], b4l[2][4];
                #pragma unroll
                for (int u = 0; u < 2; u++) {
                    int ng = np*2 + u;
                    unsigned offB = (unsigned)(((sb + wn*64 + ng*16 + lra)*GSTR + col) * 2);
                    ldsm_x4(b4h[u], uBh + offB);
                    ldsm_x4(b4l[u], uBl + offB);
                }
                // term 1: ah x bh
                #pragma unroll
                for (int u = 0; u < 2; u++)
                    #pragma unroll
                    for (int hf = 0; hf < 2; hf++)
                        #pragma unroll
                        for (int mi = 0; mi < 2; mi++)
                            mma_bf16(acc[mi*8 + (np*2+u)*2 + hf], ah[mi],
                                     b4h[u][hf], b4h[u][2 + hf]);
                // term 2: ah x bl
                #pragma unroll
                for (int u = 0; u < 2; u++)
                    #pragma unroll
                    for (int hf = 0; hf < 2; hf++)
                        #pragma unroll
                        for (int mi = 0; mi < 2; mi++)
                            mma_bf16(acc[mi*8 + (np*2+u)*2 + hf], ah[mi],
                                     b4l[u][hf], b4l[u][2 + hf]);
                // term 3: al x bh
                #pragma unroll
                for (int u = 0; u < 2; u++)
                    #pragma unroll
                    for (int hf = 0; hf < 2; hf++)
                        #pragma unroll
                        for (int mi = 0; mi < 2; mi++)
                            mma_bf16(acc[mi*8 + (np*2+u)*2 + hf], al2[mi],
                                     b4h[u][hf], b4h[u][2 + hf]);
            }
        }
        if (it + 1 < NIT) CP_WAIT0();
        __syncthreads();
    }

    // epilogue
    #pragma unroll
    for (int mi = 0; mi < 2; mi++) {
        #pragma unroll
        for (int ni = 0; ni < 8; ni++) {
            const float* c = acc[mi*8 + ni];
            int r0 = m0 + wm*32 + mi*16 + g;
            int c0 = n0 + wn*64 + ni*8 + 2*tig;
            #pragma unroll
            for (int half = 0; half < 2; half++) {
                int r = r0 + half*8;
                float v0 = c[half*2], v1 = c[half*2 + 1];
                if (MODE == 1) {
                    size_t o = (size_t)r * CC + c0;
                    float2 xv = *(const float2*)&X[o];
                    *(float2*)&out0[o] = make_float2(xv.x + v0, xv.y + v1);
                } else if (sel < 2) {
                    int b = r >> 11, t = r & 2047, h = c0 >> 7, d = c0 & 127;
                    float* outp = sel ? out1 : out0;
                    *(float2*)&outp[(((size_t)(b*HH + h) * TT) + t) * DD + d] =
                        make_float2(v0, v1);
                } else {
                    int b = r >> 11, t = r & 2047, h = c0 >> 7, d = c0 & 127;
                    size_t rb = ((size_t)((b*HH + h)*DD + d)) * TT + t;
                    __nv_bfloat16 h0 = __float2bfloat16(v0);
                    __nv_bfloat16 h1 = __float2bfloat16(v1);
                    oh[rb]      = h0;
                    ol[rb]      = __float2bfloat16(v0 - __bfloat162float(h0));
                    oh[rb + TT] = h1;
                    ol[rb + TT] = __float2bfloat16(v1 - __bfloat162float(h1));
                }
            }
        }
    }
}

// ---------------------------------------------------------------------------
// RoPE on q,k: read fp32 head-major, write bf16 hi/lo planes + qp/kp
// ---------------------------------------------------------------------------
__global__ __launch_bounds__(128) void rope_kernel(
    const float* __restrict__ qf, const float* __restrict__ kf,
    const float* __restrict__ dirs,
    __nv_bfloat16* __restrict__ qh, __nv_bfloat16* __restrict__ ql,
    __nv_bfloat16* __restrict__ kh, __nv_bfloat16* __restrict__ kl,
    float* __restrict__ qp, float* __restrict__ kp)
{
    int idx = blockIdx.x;
    int t = idx & (TT - 1);
    int h = (idx >> 11) & (HH - 1);
    int tid = threadIdx.x;
    int i = tid & 63;
    bool isq = tid < 64;
    const float* src = (isq ? qf : kf) + (size_t)idx * DD;
    __nv_bfloat16* dh = isq ? qh : kh;
    __nv_bfloat16* dl = isq ? ql : kl;
    float x1 = src[i], x2 = src[i + 64];
    float inv = expf(-9.210340371976184f * (float)i * (1.f / 64.f));
    float ang = (float)t * inv;
    float sn, cs;
    sincosf(ang, &sn, &cs);
    float y1 = x1 * cs - x2 * sn;
    float y2 = x2 * cs + x1 * sn;
    size_t o = (size_t)idx * DD;
    __nv_bfloat16 h1 = __float2bfloat16(y1);
    __nv_bfloat16 h2 = __float2bfloat16(y2);
    dh[o + i]      = h1;
    dl[o + i]      = __float2bfloat16(y1 - __bfloat162float(h1));
    dh[o + i + 64] = h2;
    dl[o + i + 64] = __float2bfloat16(y2 - __bfloat162float(h2));
    __shared__ float red[6];
    if (i < 3) red[(tid >> 6) * 3 + i] = y1 * dirs[h * 3 + i];
    __syncthreads();
    if (tid == 0)  qp[idx] = red[0] + red[1] + red[2];
    if (tid == 64) kp[idx] = red[3] + red[4] + red[5];
}

// ---------------------------------------------------------------------------
// ONE-PASS dual-softmax flash attention, term-major MMA ordering.
// Br=128 (256 thr, 8 warps, warp owns 16 rows), Bc=64.
// ---------------------------------------------------------------------------
#define KSTR 136
#define VSTR 72
#define Q_ELE (2*128*KSTR)
#define K_ELE (2*2*64*KSTR)
#define V_ELE (2*2*128*VSTR)
#define ATTN_SMEM ((Q_ELE + K_ELE + V_ELE)*2 + 2*64*4)
#define SCALE 0.08838834764831845f

__global__ __launch_bounds__(256, 1) void attn_mma(
    const __nv_bfloat16* __restrict__ qh, const __nv_bfloat16* __restrict__ ql,
    const __nv_bfloat16* __restrict__ kh, const __nv_bfloat16* __restrict__ kl,
    const __nv_bfloat16* __restrict__ vth, const __nv_bfloat16* __restrict__ vtl,
    const float* __restrict__ qp, const float* __restrict__ kp,
    const float* __restrict__ hsc,
    __nv_bfloat16* __restrict__ aoh, __nv_bfloat16* __restrict__ aol)
{
    extern __shared__ unsigned char sma[];
    __nv_bfloat16* Qh = (__nv_bfloat16*)sma;
    __nv_bfloat16* Kb = Qh + Q_ELE;
    __nv_bfloat16* Vb = Kb + K_ELE;
    float* kps = (float*)(Vb + V_ELE);

    unsigned uQ = (unsigned)__cvta_generic_to_shared(Qh);
    unsigned uK = (unsigned)__cvta_generic_to_shared(Kb);
    unsigned uV = (unsigned)__cvta_generic_to_shared(Vb);
    unsigned uKps = (unsigned)__cvta_generic_to_shared(kps);

    int bh = blockIdx.y;
    int b = bh >> 3, h = bh & 7;
    int q0 = (gridDim.x - 1 - blockIdx.x) << 7;
    size_t tb = (size_t)bh * TT;
    int tid = threadIdx.x;
    int lane = tid & 31, warp = tid >> 5;
    int g = lane >> 2, tig = lane & 3;
    int r0loc = warp*16 + g, r1loc = r0loc + 8;
    int lra = ((lane >> 3) & 1) * 8 + (lane & 7);
    int lca = (lane >> 4) * 8;

    {
        const __nv_bfloat16* qhg = qh + (tb + q0) * DD;
        const __nv_bfloat16* qlg = ql + (tb + q0) * DD;
        for (int i = tid; i < 2048; i += 256) {
            int r = i >> 4, c = (i & 15) << 3;
            *(uint4*)&Qh[r*KSTR + c]         = *(const uint4*)&qhg[r*DD + c];
            *(uint4*)&Qh[(128 + r)*KSTR + c] = *(const uint4*)&qlg[r*DD + c];
        }
    }
    float hs  = hsc[h];
    float qp0 = qp[tb + q0 + r0loc];
    float qp1 = qp[tb + q0 + r1loc];
    int ntiles = (q0 >> 6) + 2;

    auto prefetch = [&](int st, int n0) {
        const __nv_bfloat16* khg = kh + (tb + n0) * DD;
        const __nv_bfloat16* klg = kl + (tb + n0) * DD;
        for (int i = tid; i < 1024; i += 256) {
            int r = i >> 4, c = (i & 15) << 3;
            CP16(uK + (unsigned)(((st*128 + r)*KSTR + c) * 2),      khg + r*DD + c);
            CP16(uK + (unsigned)(((st*128 + 64 + r)*KSTR + c) * 2), klg + r*DD + c);
        }
        const __nv_bfloat16* vhg = vth + (size_t)bh*DD*TT + n0;
        const __nv_bfloat16* vlg = vtl + (size_t)bh*DD*TT + n0;
        for (int i = tid; i < 1024; i += 256) {
            int d = i >> 3, c = (i & 7) << 3;
            CP16(uV + (unsigned)(((st*256 + d)*VSTR + c) * 2),       vhg + (size_t)d*TT + c);
            CP16(uV + (unsigned)(((st*256 + 128 + d)*VSTR + c) * 2), vlg + (size_t)d*TT + c);
        }
        if (tid < 64) CP4(uKps + (unsigned)((st*64 + tid) * 4), kp + tb + n0 + tid);
    };

    float O[16][4], Og[16][4];
    #pragma unroll
    for (int i = 0; i < 16; i++)
        #pragma unroll
        for (int j = 0; j < 4; j++) { O[i][j] = 0.f; Og[i][j] = 0.f; }
    float l0 = 0.f, l1 = 0.f, lg0 = 0.f, lg1 = 0.f;

    prefetch(0, 0);
    CP_COMMIT();
    for (int it = 0; it < ntiles; it++) {
        int st = it & 1;
        int n0 = it << 6;
        if (it + 1 < ntiles) { prefetch(st ^ 1, (it + 1) << 6); CP_COMMIT(); CP_WAIT1(); }
        else                 { CP_WAIT0(); }
        __syncthreads();

        // ---- S = Q K^T (3xBF16), term-major (same-acc distance 4)
        float s[8][4];
        #pragma unroll
        for (int i = 0; i < 8; i++)
            #pragma unroll
            for (int j = 0; j < 4; j++) s[i][j] = 0.f;
        #pragma unroll
        for (int kk = 0; kk < 8; kk++) {
            int col = kk*16 + lca;
            unsigned qoff = (unsigned)(((warp*16 + lra)*KSTR + col) * 2);
            unsigned qa[4], qb[4];
            ldsm_x4(qa, uQ + qoff);
            ldsm_x4(qb, uQ + qoff + (unsigned)(128*KSTR*2));
            #pragma unroll
            for (int np = 0; np < 2; np++) {
                unsigned kh4[2][4], kl4[2][4];
                #pragma unroll
                for (int u = 0; u < 2; u++) {
                    int ng = np*2 + u;
                    unsigned koff = (unsigned)(((st*128 + ng*16 + lra)*KSTR + col) * 2);
                    ldsm_x4(kh4[u], uK + koff);
                    ldsm_x4(kl4[u], uK + koff + (unsigned)(64*KSTR*2));
                }
                #pragma unroll
                for (int u = 0; u < 2; u++)
                    #pragma unroll
                    for (int hf = 0; hf < 2; hf++)
                        mma_bf16(s[(np*2+u)*2 + hf], qa, kh4[u][hf], kh4[u][2 + hf]);
                #pragma unroll
                for (int u = 0; u < 2; u++)
                    #pragma unroll
                    for (int hf = 0; hf < 2; hf++)
                        mma_bf16(s[(np*2+u)*2 + hf], qa, kl4[u][hf], kl4[u][2 + hf]);
                #pragma unroll
                for (int u = 0; u < 2; u++)
                    #pragma unroll
                    for (int hf = 0; hf < 2; hf++)
                        mma_bf16(s[(np*2+u)*2 + hf], qb, kh4[u][hf], kh4[u][2 + hf]);
            }
        }

        int relq = q0 - n0;
        #pragma unroll
        for (int ni = 0; ni < 8; ni++) {
            #pragma unroll
            for (int j = 0; j < 4; j++) {
                int cl = ni*8 + 2*tig + (j & 1);
                int rl = (j < 2) ? r0loc : r1loc;
                bool ok = (cl - rl <= relq);
                float e = ok ? __expf(s[ni][j] * SCALE) : 0.f;
                s[ni][j] = e;
                if (j < 2) l0 += e; else l1 += e;
            }
        }

        const float* kpst = kps + st*64;
        #pragma unroll
        for (int kc = 0; kc < 4; kc++) {
            unsigned ph[4], pl[4], gh[4], gl[4];
            split2(s[2*kc][0],   s[2*kc][1],   ph[0], pl[0]);
            split2(s[2*kc][2],   s[2*kc][3],   ph[1], pl[1]);
            split2(s[2*kc+1][0], s[2*kc+1][1], ph[2], pl[2]);
            split2(s[2*kc+1][2], s[2*kc+1][3], ph[3], pl[3]);
            {
                int c0 = kc*16 + 2*tig;
                float k0v = kpst[c0],     k1v = kpst[c0 + 1];
                float k8v = kpst[c0 + 8], k9v = kpst[c0 + 9];
                float ge00 = (c0     - r0loc <= relq) ? __expf(qp0 * k0v) : 0.f;
                float ge01 = (c0 + 1 - r0loc <= relq) ? __expf(qp0 * k1v) : 0.f;
                float ge10 = (c0     - r1loc <= relq) ? __expf(qp1 * k0v) : 0.f;
                float ge11 = (c0 + 1 - r1loc <= relq) ? __expf(qp1 * k1v) : 0.f;
                float ge08 = (c0 + 8 - r0loc <= relq) ? __expf(qp0 * k8v) : 0.f;
                float ge09 = (c0 + 9 - r0loc <= relq) ? __expf(qp0 * k9v) : 0.f;
                float ge18 = (c0 + 8 - r1loc <= relq) ? __expf(qp1 * k8v) : 0.f;
                float ge19 = (c0 + 9 - r1loc <= relq) ? __expf(qp1 * k9v) : 0.f;
                lg0 += ge00 + ge01 + ge08 + ge09;
                lg1 += ge10 + ge11 + ge18 + ge19;
                split2(ge00, ge01, gh[0], gl[0]);
                split2(ge10, ge11, gh[1], gl[1]);
                split2(ge08, ge09, gh[2], gl[2]);
                split2(ge18, ge19, gh[3], gl[3]);
            }
            // PV: term-major per ndg (same-acc distance 4)
            #pragma unroll
            for (int ndg = 0; ndg < 8; ndg++) {
                unsigned voff = (unsigned)(((st*256 + ndg*16 + lra)*VSTR + kc*16 + lca) * 2);
                unsigned vh4[4], vl4[4];
                ldsm_x4(vh4, uV + voff);
                ldsm_x4(vl4, uV + voff + (unsigned)(128*VSTR*2));
                int nd0 = ndg*2, nd1 = ndg*2 + 1;
                // term 1: P_hi x V_hi
                mma_bf16(O[nd0],  ph, vh4[0], vh4[2]);
                mma_bf16(O[nd1],  ph, vh4[1], vh4[3]);
                mma_bf16(Og[nd0], gh, vh4[0], vh4[2]);
                mma_bf16(Og[nd1], gh, vh4[1], vh4[3]);
                // term 2: P_hi x V_lo
                mma_bf16(O[nd0],  ph, vl4[0], vl4[2]);
                mma_bf16(O[nd1],  ph, vl4[1], vl4[3]);
                mma_bf16(Og[nd0], gh, vl4[0], vl4[2]);
                mma_bf16(Og[nd1], gh, vl4[1], vl4[3]);
                // term 3: P_lo x V_hi
                mma_bf16(O[nd0],  pl, vh4[0], vh4[2]);
                mma_bf16(O[nd1],  pl, vh4[1], vh4[3]);
                mma_bf16(Og[nd0], gl, vh4[0], vh4[2]);
                mma_bf16(Og[nd1], gl, vh4[1], vh4[3]);
            }
        }
        __syncthreads();
    }

    #pragma unroll
    for (int o = 1; o <= 2; o <<= 1) {
        l0  += __shfl_xor_sync(0xffffffffu, l0,  o);
        l1  += __shfl_xor_sync(0xffffffffu, l1,  o);
        lg0 += __shfl_xor_sync(0xffffffffu, lg0, o);
        lg1 += __shfl_xor_sync(0xffffffffu, lg1, o);
    }
    float c1a = (1.f - hs) / l0, c2a = hs / lg0;
    float c1b = (1.f - hs) / l1, c2b = hs / lg1;

    size_t orow0 = (size_t)(b*TT + q0 + r0loc) * CC + h*DD;
    size_t orow1 = (size_t)(b*TT + q0 + r1loc) * CC + h*DD;
    #pragma unroll
    for (int nd = 0; nd < 16; nd++) {
        int d0 = nd*8 + 2*tig;
        unsigned hh, ll;
        float v0 = c1a*O[nd][0] + c2a*Og[nd][0];
        float v1 = c1a*O[nd][1] + c2a*Og[nd][1];
        split2(v0, v1, hh, ll);
        *(unsigned*)&aoh[orow0 + d0] = hh;
        *(unsigned*)&aol[orow0 + d0] = ll;
        v0 = c1b*O[nd][2] + c2b*Og[nd][2];
        v1 = c1b*O[nd][3] + c2b*Og[nd][3];
        split2(v0, v1, hh, ll);
        *(unsigned*)&aoh[orow1 + d0] = hh;
        *(unsigned*)&aol[orow1 + d0] = ll;
    }
}

// ---------------------------------------------------------------------------
// Launcher
// ---------------------------------------------------------------------------
extern "C" void kernel_launch(void* const* d_in, const int* in_sizes, int n_in,
                              void* d_out, int out_size)
{
    const float* x   = (const float*)d_in[0];
    const float* Wq  = (const float*)d_in[1];
    const float* Wk  = (const float*)d_in[2];
    const float* Wv  = (const float*)d_in[3];
    const float* Wo  = (const float*)d_in[4];
    const float* lng = (const float*)d_in[5];
    const float* lnb = (const float*)d_in[6];
    const float* hsc = (const float*)d_in[7];
    const float* hdr = (const float*)d_in[8];
    float* out = (float*)d_out;

    unsigned char* base = nullptr;
    cudaGetSymbolAddress((void**)&base, g_scratch);
    __nv_bfloat16* xnh = (__nv_bfloat16*)(base + OFF_XNH);
    __nv_bfloat16* xnl = (__nv_bfloat16*)(base + OFF_XNL);
    __nv_bfloat16* wh  = (__nv_bfloat16*)(base + OFF_WH);
    __nv_bfloat16* wl  = (__nv_bfloat16*)(base + OFF_WL);
    float* qf = (float*)(base + OFF_QF);
    float* kf = (float*)(base + OFF_KF);
    __nv_bfloat16* qhp = (__nv_bfloat16*)(base + OFF_QH);
    __nv_bfloat16* qlp = (__nv_bfloat16*)(base + OFF_QL);
    __nv_bfloat16* khp = (__nv_bfloat16*)(base + OFF_KH);
    __nv_bfloat16* klp = (__nv_bfloat16*)(base + OFF_KL);
    __nv_bfloat16* vth = (__nv_bfloat16*)(base + OFF_VTH);
    __nv_bfloat16* vtl = (__nv_bfloat16*)(base + OFF_VTL);
    __nv_bfloat16* aoh = (__nv_bfloat16*)(base + OFF_AOH);
    __nv_bfloat16* aol = (__nv_bfloat16*)(base + OFF_AOL);
    float* gqp = (float*)(base + OFF_QP);
    float* gkp = (float*)(base + OFF_KP);

    cudaFuncSetAttribute(gemm2<0>,
                         cudaFuncAttributeMaxDynamicSharedMemorySize, GEMM_SMEM);
    cudaFuncSetAttribute(gemm2<1>,
                         cudaFuncAttributeMaxDynamicSharedMemorySize, GEMM_SMEM);
    cudaFuncSetAttribute(attn_mma,
                         cudaFuncAttributeMaxDynamicSharedMemorySize, ATTN_SMEM);

    ln_split<<<NTOK, 256>>>(x, lng, lnb, xnh, xnl);
    wsplit<<<4096, 256>>>(Wq, Wk, Wv, Wo, wh, wl);

    gemm2<0><<<dim3(24, NTOK/128), 256, GEMM_SMEM>>>(
        xnh, xnl, wh, wl, nullptr, qf, kf, vth, vtl);

    rope_kernel<<<BH*TT, 128>>>(qf, kf, hdr, qhp, qlp, khp, klp, gqp, gkp);

    attn_mma<<<dim3(TT/128, BH), 256, ATTN_SMEM>>>(qhp, qlp, khp, klp, vth, vtl,
                                                   gqp, gkp, hsc, aoh, aol);

    gemm2<1><<<dim3(8, NTOK/128), 256, GEMM_SMEM>>>(
        aoh, aol, wh + 3*WPL, wl + 3*WPL, x, out, nullptr, nullptr, nullptr);
}

// round 13
// speedup vs baseline: 1.1965x; 1.1965x over previous
#include <cuda_runtime.h>
#include <cuda_fp16.h>
#include <math.h>

// Problem constants
#define BB 4
#define TT 2048
#define CC 1024
#define HH 8
#define DD 128
#define NTOK (BB*TT)          // 8192
#define BH   (BB*HH)          // 32
#define WPL  ((size_t)CC*CC)  // weight plane elems

// ---------------------------------------------------------------------------
// Scratch
// ---------------------------------------------------------------------------
#define SZ_F32 ((size_t)NTOK*CC*4)
#define SZ_BF  ((size_t)NTOK*CC*2)
#define SZ_WPL ((size_t)4*CC*CC*2)
#define SZ_P   ((size_t)BH*TT*4)
#define SZ_CS  ((size_t)TT*64*8)

#define OFF_XNH ((size_t)0)
#define OFF_XNL (OFF_XNH + SZ_BF)
#define OFF_WH  (OFF_XNL + SZ_BF)
#define OFF_WL  (OFF_WH + SZ_WPL)
#define OFF_QF  (OFF_WL + SZ_WPL)
#define OFF_KF  (OFF_QF + SZ_F32)
#define OFF_QH  (OFF_KF + SZ_F32)
#define OFF_QL  (OFF_QH + SZ_BF)
#define OFF_KH  (OFF_QL + SZ_BF)
#define OFF_KL  (OFF_KH + SZ_BF)
#define OFF_VTH (OFF_KL + SZ_BF)
#define OFF_VTL (OFF_VTH + SZ_BF)
#define OFF_AOH (OFF_VTL + SZ_BF)
#define OFF_QP  (OFF_AOH + SZ_BF)
#define OFF_KP  (OFF_QP + SZ_P)
#define OFF_CS  (OFF_KP + SZ_P)
#define SCRATCH_BYTES (OFF_CS + SZ_CS)

__device__ __align__(256) unsigned char g_scratch[SCRATCH_BYTES];

// ---------------------------------------------------------------------------
// helpers (fp16 MMA path)
// ---------------------------------------------------------------------------
__device__ __forceinline__ void mma_f16(float* c, const unsigned* a,
                                        unsigned b0, unsigned b1) {
    asm volatile(
        "mma.sync.aligned.m16n8k16.row.col.f32.f16.f16.f32 "
        "{%0,%1,%2,%3},{%4,%5,%6,%7},{%8,%9},{%0,%1,%2,%3};"
        : "+f"(c[0]), "+f"(c[1]), "+f"(c[2]), "+f"(c[3])
        : "r"(a[0]), "r"(a[1]), "r"(a[2]), "r"(a[3]), "r"(b0), "r"(b1));
}

__device__ __forceinline__ void ldsm_x4(unsigned r[4], unsigned addr) {
    asm volatile("ldmatrix.sync.aligned.m8n8.x4.shared.b16 {%0,%1,%2,%3}, [%4];"
        : "=r"(r[0]), "=r"(r[1]), "=r"(r[2]), "=r"(r[3]) : "r"(addr));
}

#define CP16(dst, src) \
    asm volatile("cp.async.cg.shared.global [%0], [%1], 16;" :: "r"(dst), "l"(src))
#define CP4(dst, src) \
    asm volatile("cp.async.ca.shared.global [%0], [%1], 4;" :: "r"(dst), "l"(src))
#define CP_COMMIT() asm volatile("cp.async.commit_group;")
#define CP_WAIT0()  asm volatile("cp.async.wait_group 0;")
#define CP_WAIT1()  asm volatile("cp.async.wait_group 1;")

// fp16 hi/lo split of two floats
__device__ __forceinline__ void split2(float a, float b, unsigned& hi, unsigned& lo) {
    __half2 h = __floats2half2_rn(a, b);
    float la = a - __half2float(__low2half(h));
    float lb = b - __half2float(__high2half(h));
    __half2 l = __floats2half2_rn(la, lb);
    hi = *(unsigned*)&h;
    lo = *(unsigned*)&l;
}

// plain fp16 pack of two floats
__device__ __forceinline__ unsigned pack2(float a, float b) {
    __half2 h = __floats2half2_rn(a, b);
    return *(unsigned*)&h;
}

// ---------------------------------------------------------------------------
// LayerNorm -> fp16 hi/lo planes
// ---------------------------------------------------------------------------
__global__ __launch_bounds__(256) void ln_split(
    const float* __restrict__ x, const float* __restrict__ gam,
    const float* __restrict__ bet,
    __half* __restrict__ xnh, __half* __restrict__ xnl)
{
    int row = blockIdx.x;
    int t   = threadIdx.x;
    const float4* xr = (const float4*)(x + (size_t)row * CC);
    float4 v = xr[t];
    float s  = v.x + v.y + v.z + v.w;
    float ss = v.x*v.x + v.y*v.y + v.z*v.z + v.w*v.w;
    #pragma unroll
    for (int o = 16; o; o >>= 1) {
        s  += __shfl_xor_sync(0xffffffffu, s,  o);
        ss += __shfl_xor_sync(0xffffffffu, ss, o);
    }
    __shared__ float ws[8], wss[8];
    int wid = t >> 5;
    if ((t & 31) == 0) { ws[wid] = s; wss[wid] = ss; }
    __syncthreads();
    s = 0.f; ss = 0.f;
    #pragma unroll
    for (int i = 0; i < 8; i++) { s += ws[i]; ss += wss[i]; }
    float mu  = s * (1.f / CC);
    float var = ss * (1.f / CC) - mu * mu;
    float inv = rsqrtf(var + 1e-5f);
    float4 g4 = ((const float4*)gam)[t];
    float4 b4 = ((const float4*)bet)[t];
    float4 o;
    o.x = (v.x - mu) * inv * g4.x + b4.x;
    o.y = (v.y - mu) * inv * g4.y + b4.y;
    o.z = (v.z - mu) * inv * g4.z + b4.z;
    o.w = (v.w - mu) * inv * g4.w + b4.w;
    unsigned h0, l0, h1, l1;
    split2(o.x, o.y, h0, l0);
    split2(o.z, o.w, h1, l1);
    size_t off = (size_t)row * CC + t*4;
    *(uint2*)&xnh[off] = make_uint2(h0, h1);
    *(uint2*)&xnl[off] = make_uint2(l0, l1);
}

// ---------------------------------------------------------------------------
// Split 4 weight matrices into fp16 hi/lo planes: plane order Wq,Wk,Wv,Wo
// ---------------------------------------------------------------------------
__global__ __launch_bounds__(256) void wsplit(
    const float* __restrict__ w0, const float* __restrict__ w1,
    const float* __restrict__ w2, const float* __restrict__ w3,
    __half* __restrict__ wh, __half* __restrict__ wl)
{
    int mid = blockIdx.x >> 10;
    const float* src = (mid == 0) ? w0 : (mid == 1) ? w1 : (mid == 2) ? w2 : w3;
    size_t idx = ((size_t)(blockIdx.x & 1023))*1024 + threadIdx.x*4;
    float4 v = *(const float4*)(src + idx);
    unsigned h0, l0, h1, l1;
    split2(v.x, v.y, h0, l0);
    split2(v.z, v.w, h1, l1);
    size_t off = (size_t)mid*WPL + idx;
    *(uint2*)&wh[off] = make_uint2(h0, h1);
    *(uint2*)&wl[off] = make_uint2(l0, l1);
}

// ---------------------------------------------------------------------------
// rope cos/sin table: cs[t*64+i] = (cos(t*inv_i), sin(t*inv_i))
// ---------------------------------------------------------------------------
__global__ __launch_bounds__(64) void rope_tab(float2* __restrict__ cs)
{
    int t = blockIdx.x, i = threadIdx.x;
    float inv = expf(-9.210340371976184f * (float)i * (1.f / 64.f));
    float sn, co;
    sincosf((float)t * inv, &sn, &co);
    cs[t*64 + i] = make_float2(co, sn);
}

// ---------------------------------------------------------------------------
// fp16 GEMM: cp.async double buffer + ldmatrix, 128x128x32, 2 CTA/SM.
// Terms: t1 = ah*bh, t2 = ah*bl, t3 = al*bh.
// MODE 0: QKV fused (grid.x=24; sel = x>>3): sel 0/1 (Q/K) -> 3 terms,
//         fp32 head-major out; sel 2 (V) -> 2 terms, transposed fp16
//         hi/lo planes [B,H,D,T]
// MODE 1: Wo, 2 terms, out0 = X + acc (fp32 row-major)
// ---------------------------------------------------------------------------
#define GSTR 40
#define GEMM_SMEM (4*2*128*GSTR*2)   // 81920 B

template<int MODE>
__global__ __launch_bounds__(256, 2) void gemm2(
    const __half* __restrict__ Ah, const __half* __restrict__ Al,
    const __half* __restrict__ Wh, const __half* __restrict__ Wl,
    const float* __restrict__ X,
    float* __restrict__ out0, float* __restrict__ out1,
    __half* __restrict__ oh, __half* __restrict__ ol)
{
    extern __shared__ __half smb[];
    __half* sAh = smb;
    __half* sAl = sAh + 2*128*GSTR;
    __half* sBh = sAl + 2*128*GSTR;
    __half* sBl = sBh + 2*128*GSTR;
    unsigned uAh = (unsigned)__cvta_generic_to_shared(sAh);
    unsigned uAl = (unsigned)__cvta_generic_to_shared(sAl);
    unsigned uBh = (unsigned)__cvta_generic_to_shared(sBh);
    unsigned uBl = (unsigned)__cvta_generic_to_shared(sBl);

    int tid = threadIdx.x, lane = tid & 31, warp = tid >> 5;
    int g = lane >> 2, tig = lane & 3;
    int wm = warp >> 1, wn = warp & 1;
    int sel = (MODE == 0) ? (blockIdx.x >> 3) : 0;
    int n0 = (MODE == 0) ? ((blockIdx.x & 7) << 7) : (blockIdx.x << 7);
    int m0 = blockIdx.y << 7;
    const __half* Wph = Wh + (size_t)sel*WPL;
    const __half* Wpl = Wl + (size_t)sel*WPL;
    bool term3 = (MODE == 0) && (sel < 2);

    int lr = tid >> 2;
    int lc8 = (tid & 3) * 8;

    float acc[16][4];
    #pragma unroll
    for (int i = 0; i < 16; i++)
        #pragma unroll
        for (int j = 0; j < 4; j++) acc[i][j] = 0.f;

    auto load_stage = [&](int buf, int k0) {
        size_t a0 = (size_t)(m0 + lr) * CC + k0 + lc8;
        size_t b0 = (size_t)(n0 + lr) * CC + k0 + lc8;
        unsigned d0 = (unsigned)(((buf*128 + lr)*GSTR + lc8) * 2);
        unsigned d1 = (unsigned)(((buf*128 + lr + 64)*GSTR + lc8) * 2);
        CP16(uAh + d0, Ah + a0);  CP16(uAh + d1, Ah + a0 + (size_t)64*CC);
        if (MODE == 0) {
            CP16(uAl + d0, Al + a0);  CP16(uAl + d1, Al + a0 + (size_t)64*CC);
        }
        CP16(uBh + d0, Wph + b0); CP16(uBh + d1, Wph + b0 + (size_t)64*CC);
        CP16(uBl + d0, Wpl + b0); CP16(uBl + d1, Wpl + b0 + (size_t)64*CC);
    };

    load_stage(0, 0);
    CP_COMMIT();
    CP_WAIT0();
    __syncthreads();

    int lra = ((lane >> 3) & 1) * 8 + (lane & 7);
    int lca = (lane >> 4) * 8;
    const int NIT = CC / 32;

    for (int it = 0; it < NIT; it++) {
        int buf = it & 1;
        if (it + 1 < NIT) { load_stage(buf ^ 1, (it + 1) * 32); CP_COMMIT(); }

        int sb = buf * 128;
        #pragma unroll
        for (int kk = 0; kk < 2; kk++) {
            int col = kk*16 + lca;
            unsigned ah[2][4], al2[2][4];
            #pragma unroll
            for (int mi = 0; mi < 2; mi++) {
                unsigned offA = (unsigned)(((sb + wm*32 + mi*16 + lra)*GSTR + col) * 2);
                ldsm_x4(ah[mi], uAh + offA);
                if (term3) ldsm_x4(al2[mi], uAl + offA);
            }
            #pragma unroll
            for (int np = 0; np < 2; np++) {
                unsigned b4h[2][4], b4l[2][4];
                #pragma unroll
                for (int u = 0; u < 2; u++) {
                    int ng = np*2 + u;
                    unsigned offB = (unsigned)(((sb + wn*64 + ng*16 + lra)*GSTR + col) * 2);
                    ldsm_x4(b4h[u], uBh + offB);
                    ldsm_x4(b4l[u], uBl + offB);
                }
                // term 1: ah x bh
                #pragma unroll
                for (int u = 0; u < 2; u++)
                    #pragma unroll
                    for (int hf = 0; hf < 2; hf++)
                        #pragma unroll
                        for (int mi = 0; mi < 2; mi++)
                            mma_f16(acc[mi*8 + (np*2+u)*2 + hf], ah[mi],
                                    b4h[u][hf], b4h[u][2 + hf]);
                // term 2: ah x bl
                #pragma unroll
                for (int u = 0; u < 2; u++)
                    #pragma unroll
                    for (int hf = 0; hf < 2; hf++)
                        #pragma unroll
                        for (int mi = 0; mi < 2; mi++)
                            mma_f16(acc[mi*8 + (np*2+u)*2 + hf], ah[mi],
                                    b4l[u][hf], b4l[u][2 + hf]);
                // term 3: al x bh (Q/K slices only)
                if (term3) {
                    #pragma unroll
                    for (int u = 0; u < 2; u++)
                        #pragma unroll
                        for (int hf = 0; hf < 2; hf++)
                            #pragma unroll
                            for (int mi = 0; mi < 2; mi++)
                                mma_f16(acc[mi*8 + (np*2+u)*2 + hf], al2[mi],
                                        b4h[u][hf], b4h[u][2 + hf]);
                }
            }
        }
        if (it + 1 < NIT) CP_WAIT0();
        __syncthreads();
    }

    // epilogue
    #pragma unroll
    for (int mi = 0; mi < 2; mi++) {
        #pragma unroll
        for (int ni = 0; ni < 8; ni++) {
            const float* c = acc[mi*8 + ni];
            int r0 = m0 + wm*32 + mi*16 + g;
            int c0 = n0 + wn*64 + ni*8 + 2*tig;
            #pragma unroll
            for (int half = 0; half < 2; half++) {
                int r = r0 + half*8;
                float v0 = c[half*2], v1 = c[half*2 + 1];
                if (MODE == 1) {
                    size_t o = (size_t)r * CC + c0;
                    float2 xv = *(const float2*)&X[o];
                    *(float2*)&out0[o] = make_float2(xv.x + v0, xv.y + v1);
                } else if (sel < 2) {
                    int b = r >> 11, t = r & 2047, h = c0 >> 7, d = c0 & 127;
                    float* outp = sel ? out1 : out0;
                    *(float2*)&outp[(((size_t)(b*HH + h) * TT) + t) * DD + d] =
                        make_float2(v0, v1);
                } else {
                    int b = r >> 11, t = r & 2047, h = c0 >> 7, d = c0 & 127;
                    size_t rb = ((size_t)((b*HH + h)*DD + d)) * TT + t;
                    __half h0 = __float2half_rn(v0);
                    __half h1 = __float2half_rn(v1);
                    oh[rb]      = h0;
                    ol[rb]      = __float2half_rn(v0 - __half2float(h0));
                    oh[rb + TT] = h1;
                    ol[rb + TT] = __float2half_rn(v1 - __half2float(h1));
                }
            }
        }
    }
}

// ---------------------------------------------------------------------------
// RoPE on q,k: read fp32 head-major, write fp16 hi/lo planes + qp/kp.
// Angles come from the precomputed cos/sin table.
// ---------------------------------------------------------------------------
__global__ __launch_bounds__(128) void rope_kernel(
    const float* __restrict__ qf, const float* __restrict__ kf,
    const float* __restrict__ dirs, const float2* __restrict__ cs,
    __half* __restrict__ qh, __half* __restrict__ ql,
    __half* __restrict__ kh, __half* __restrict__ kl,
    float* __restrict__ qp, float* __restrict__ kp)
{
    int idx = blockIdx.x;
    int t = idx & (TT - 1);
    int h = (idx >> 11) & (HH - 1);
    int tid = threadIdx.x;
    int i = tid & 63;
    bool isq = tid < 64;
    const float* src = (isq ? qf : kf) + (size_t)idx * DD;
    __half* dh = isq ? qh : kh;
    __half* dl = isq ? ql : kl;
    float x1 = src[i], x2 = src[i + 64];
    float2 cssn = cs[t*64 + i];
    float y1 = x1 * cssn.x - x2 * cssn.y;
    float y2 = x2 * cssn.x + x1 * cssn.y;
    size_t o = (size_t)idx * DD;
    __half h1 = __float2half_rn(y1);
    __half h2 = __float2half_rn(y2);
    dh[o + i]      = h1;
    dl[o + i]      = __float2half_rn(y1 - __half2float(h1));
    dh[o + i + 64] = h2;
    dl[o + i + 64] = __float2half_rn(y2 - __half2float(h2));
    __shared__ float red[6];
    if (i < 3) red[(tid >> 6) * 3 + i] = y1 * dirs[h * 3 + i];
    __syncthreads();
    if (tid == 0)  qp[idx] = red[0] + red[1] + red[2];
    if (tid == 64) kp[idx] = red[3] + red[4] + red[5];
}

// ---------------------------------------------------------------------------
// ONE-PASS dual-softmax flash attention, fp16 MMA.
// S: 3-term fp16 (score path). PV: 2-term (P_hi x (V_hi + V_lo)), both O & Og.
// Br=128 (256 thr, 8 warps, warp owns 16 rows), Bc=64.
// ---------------------------------------------------------------------------
#define KSTR 136
#define VSTR 72
#define Q_ELE (2*128*KSTR)
#define K_ELE (2*2*64*KSTR)
#define V_ELE (2*2*128*VSTR)
#define ATTN_SMEM ((Q_ELE + K_ELE + V_ELE)*2 + 2*64*4)
#define SCALE 0.08838834764831845f

__global__ __launch_bounds__(256, 1) void attn_mma(
    const __half* __restrict__ qh, const __half* __restrict__ ql,
    const __half* __restrict__ kh, const __half* __restrict__ kl,
    const __half* __restrict__ vth, const __half* __restrict__ vtl,
    const float* __restrict__ qp, const float* __restrict__ kp,
    const float* __restrict__ hsc,
    __half* __restrict__ aoh)
{
    extern __shared__ unsigned char sma[];
    __half* Qh = (__half*)sma;
    __half* Kb = Qh + Q_ELE;
    __half* Vb = Kb + K_ELE;
    float* kps = (float*)(Vb + V_ELE);

    unsigned uQ = (unsigned)__cvta_generic_to_shared(Qh);
    unsigned uK = (unsigned)__cvta_generic_to_shared(Kb);
    unsigned uV = (unsigned)__cvta_generic_to_shared(Vb);
    unsigned uKps = (unsigned)__cvta_generic_to_shared(kps);

    int bh = blockIdx.y;
    int b = bh >> 3, h = bh & 7;
    int q0 = (gridDim.x - 1 - blockIdx.x) << 7;
    size_t tb = (size_t)bh * TT;
    int tid = threadIdx.x;
    int lane = tid & 31, warp = tid >> 5;
    int g = lane >> 2, tig = lane & 3;
    int r0loc = warp*16 + g, r1loc = r0loc + 8;
    int lra = ((lane >> 3) & 1) * 8 + (lane & 7);
    int lca = (lane >> 4) * 8;

    {
        const __half* qhg = qh + (tb + q0) * DD;
        const __half* qlg = ql + (tb + q0) * DD;
        for (int i = tid; i < 2048; i += 256) {
            int r = i >> 4, c = (i & 15) << 3;
            *(uint4*)&Qh[r*KSTR + c]         = *(const uint4*)&qhg[r*DD + c];
            *(uint4*)&Qh[(128 + r)*KSTR + c] = *(const uint4*)&qlg[r*DD + c];
        }
    }
    float hs  = hsc[h];
    float qp0 = qp[tb + q0 + r0loc];
    float qp1 = qp[tb + q0 + r1loc];
    int ntiles = (q0 >> 6) + 2;

    auto prefetch = [&](int st, int n0) {
        const __half* khg = kh + (tb + n0) * DD;
        const __half* klg = kl + (tb + n0) * DD;
        for (int i = tid; i < 1024; i += 256) {
            int r = i >> 4, c = (i & 15) << 3;
            CP16(uK + (unsigned)(((st*128 + r)*KSTR + c) * 2),      khg + r*DD + c);
            CP16(uK + (unsigned)(((st*128 + 64 + r)*KSTR + c) * 2), klg + r*DD + c);
        }
        const __half* vhg = vth + (size_t)bh*DD*TT + n0;
        const __half* vlg = vtl + (size_t)bh*DD*TT + n0;
        for (int i = tid; i < 1024; i += 256) {
            int d = i >> 3, c = (i & 7) << 3;
            CP16(uV + (unsigned)(((st*256 + d)*VSTR + c) * 2),       vhg + (size_t)d*TT + c);
            CP16(uV + (unsigned)(((st*256 + 128 + d)*VSTR + c) * 2), vlg + (size_t)d*TT + c);
        }
        if (tid < 64) CP4(uKps + (unsigned)((st*64 + tid) * 4), kp + tb + n0 + tid);
    };

    float O[16][4], Og[16][4];
    #pragma unroll
    for (int i = 0; i < 16; i++)
        #pragma unroll
        for (int j = 0; j < 4; j++) { O[i][j] = 0.f; Og[i][j] = 0.f; }
    float l0 = 0.f, l1 = 0.f, lg0 = 0.f, lg1 = 0.f;

    prefetch(0, 0);
    CP_COMMIT();
    for (int it = 0; it < ntiles; it++) {
        int st = it & 1;
        int n0 = it << 6;
        if (it + 1 < ntiles) { prefetch(st ^ 1, (it + 1) << 6); CP_COMMIT(); CP_WAIT1(); }
        else                 { CP_WAIT0(); }
        __syncthreads();

        // ---- S = Q K^T (3-term fp16)
        float s[8][4];
        #pragma unroll
        for (int i = 0; i < 8; i++)
            #pragma unroll
            for (int j = 0; j < 4; j++) s[i][j] = 0.f;
        #pragma unroll
        for (int kk = 0; kk < 8; kk++) {
            int col = kk*16 + lca;
            unsigned qoff = (unsigned)(((warp*16 + lra)*KSTR + col) * 2);
            unsigned qa[4], qb[4];
            ldsm_x4(qa, uQ + qoff);
            ldsm_x4(qb, uQ + qoff + (unsigned)(128*KSTR*2));
            #pragma unroll
            for (int np = 0; np < 2; np++) {
                unsigned kh4[2][4], kl4[2][4];
                #pragma unroll
                for (int u = 0; u < 2; u++) {
                    int ng = np*2 + u;
                    unsigned koff = (unsigned)(((st*128 + ng*16 + lra)*KSTR + col) * 2);
                    ldsm_x4(kh4[u], uK + koff);
                    ldsm_x4(kl4[u], uK + koff + (unsigned)(64*KSTR*2));
                }
                #pragma unroll
                for (int u = 0; u < 2; u++)
                    #pragma unroll
                    for (int hf = 0; hf < 2; hf++)
                        mma_f16(s[(np*2+u)*2 + hf], qa, kh4[u][hf], kh4[u][2 + hf]);
                #pragma unroll
                for (int u = 0; u < 2; u++)
                    #pragma unroll
                    for (int hf = 0; hf < 2; hf++)
                        mma_f16(s[(np*2+u)*2 + hf], qa, kl4[u][hf], kl4[u][2 + hf]);
                #pragma unroll
                for (int u = 0; u < 2; u++)
                    #pragma unroll
                    for (int hf = 0; hf < 2; hf++)
                        mma_f16(s[(np*2+u)*2 + hf], qb, kh4[u][hf], kh4[u][2 + hf]);
            }
        }

        int relq = q0 - n0;
        #pragma unroll
        for (int ni = 0; ni < 8; ni++) {
            #pragma unroll
            for (int j = 0; j < 4; j++) {
                int cl = ni*8 + 2*tig + (j & 1);
                int rl = (j < 2) ? r0loc : r1loc;
                bool ok = (cl - rl <= relq);
                float e = ok ? __expf(s[ni][j] * SCALE) : 0.f;
                s[ni][j] = e;
                if (j < 2) l0 += e; else l1 += e;
            }
        }

        const float* kpst = kps + st*64;
        #pragma unroll
        for (int kc = 0; kc < 4; kc++) {
            unsigned ph[4], gh[4];
            ph[0] = pack2(s[2*kc][0],   s[2*kc][1]);
            ph[1] = pack2(s[2*kc][2],   s[2*kc][3]);
            ph[2] = pack2(s[2*kc+1][0], s[2*kc+1][1]);
            ph[3] = pack2(s[2*kc+1][2], s[2*kc+1][3]);
            {
                int c0 = kc*16 + 2*tig;
                float k0v = kpst[c0],     k1v = kpst[c0 + 1];
                float k8v = kpst[c0 + 8], k9v = kpst[c0 + 9];
                float ge00 = (c0     - r0loc <= relq) ? __expf(qp0 * k0v) : 0.f;
                float ge01 = (c0 + 1 - r0loc <= relq) ? __expf(qp0 * k1v) : 0.f;
                float ge10 = (c0     - r1loc <= relq) ? __expf(qp1 * k0v) : 0.f;
                float ge11 = (c0 + 1 - r1loc <= relq) ? __expf(qp1 * k1v) : 0.f;
                float ge08 = (c0 + 8 - r0loc <= relq) ? __expf(qp0 * k8v) : 0.f;
                float ge09 = (c0 + 9 - r0loc <= relq) ? __expf(qp0 * k9v) : 0.f;
                float ge18 = (c0 + 8 - r1loc <= relq) ? __expf(qp1 * k8v) : 0.f;
                float ge19 = (c0 + 9 - r1loc <= relq) ? __expf(qp1 * k9v) : 0.f;
                lg0 += ge00 + ge01 + ge08 + ge09;
                lg1 += ge10 + ge11 + ge18 + ge19;
                gh[0] = pack2(ge00, ge01);
                gh[1] = pack2(ge10, ge11);
                gh[2] = pack2(ge08, ge09);
                gh[3] = pack2(ge18, ge19);
            }
            // PV: 2-term (P_hi x V_hi + P_hi x V_lo) for both O and Og
            #pragma unroll
            for (int ndg = 0; ndg < 8; ndg++) {
                unsigned voff = (unsigned)(((st*256 + ndg*16 + lra)*VSTR + kc*16 + lca) * 2);
                unsigned vh4[4], vl4[4];
                ldsm_x4(vh4, uV + voff);
                ldsm_x4(vl4, uV + voff + (unsigned)(128*VSTR*2));
                int nd0 = ndg*2, nd1 = ndg*2 + 1;
                mma_f16(O[nd0],  ph, vh4[0], vh4[2]);
                mma_f16(O[nd1],  ph, vh4[1], vh4[3]);
                mma_f16(Og[nd0], gh, vh4[0], vh4[2]);
                mma_f16(Og[nd1], gh, vh4[1], vh4[3]);
                mma_f16(O[nd0],  ph, vl4[0], vl4[2]);
                mma_f16(O[nd1],  ph, vl4[1], vl4[3]);
                mma_f16(Og[nd0], gh, vl4[0], vl4[2]);
                mma_f16(Og[nd1], gh, vl4[1], vl4[3]);
            }
        }
        __syncthreads();
    }

    #pragma unroll
    for (int o = 1; o <= 2; o <<= 1) {
        l0  += __shfl_xor_sync(0xffffffffu, l0,  o);
        l1  += __shfl_xor_sync(0xffffffffu, l1,  o);
        lg0 += __shfl_xor_sync(0xffffffffu, lg0, o);
        lg1 += __shfl_xor_sync(0xffffffffu, lg1, o);
    }
    float c1a = (1.f - hs) / l0, c2a = hs / lg0;
    float c1b = (1.f - hs) / l1, c2b = hs / lg1;

    // epilogue: fp16 plane for Wo GEMM (Wo uses 2-term, A-lo not needed)
    size_t orow0 = (size_t)(b*TT + q0 + r0loc) * CC + h*DD;
    size_t orow1 = (size_t)(b*TT + q0 + r1loc) * CC + h*DD;
    #pragma unroll
    for (int nd = 0; nd < 16; nd++) {
        int d0 = nd*8 + 2*tig;
        float v0 = c1a*O[nd][0] + c2a*Og[nd][0];
        float v1 = c1a*O[nd][1] + c2a*Og[nd][1];
        *(unsigned*)&aoh[orow0 + d0] = pack2(v0, v1);
        v0 = c1b*O[nd][2] + c2b*Og[nd][2];
        v1 = c1b*O[nd][3] + c2b*Og[nd][3];
        *(unsigned*)&aoh[orow1 + d0] = pack2(v0, v1);
    }
}

// ---------------------------------------------------------------------------
// Launcher
// ---------------------------------------------------------------------------
extern "C" void kernel_launch(void* const* d_in, const int* in_sizes, int n_in,
                              void* d_out, int out_size)
{
    const float* x   = (const float*)d_in[0];
    const float* Wq  = (const float*)d_in[1];
    const float* Wk  = (const float*)d_in[2];
    const float* Wv  = (const float*)d_in[3];
    const float* Wo  = (const float*)d_in[4];
    const float* lng = (const float*)d_in[5];
    const float* lnb = (const float*)d_in[6];
    const float* hsc = (const float*)d_in[7];
    const float* hdr = (const float*)d_in[8];
    float* out = (float*)d_out;

    unsigned char* base = nullptr;
    cudaGetSymbolAddress((void**)&base, g_scratch);
    __half* xnh = (__half*)(base + OFF_XNH);
    __half* xnl = (__half*)(base + OFF_XNL);
    __half* wh  = (__half*)(base + OFF_WH);
    __half* wl  = (__half*)(base + OFF_WL);
    float* qf = (float*)(base + OFF_QF);
    float* kf = (float*)(base + OFF_KF);
    __half* qhp = (__half*)(base + OFF_QH);
    __half* qlp = (__half*)(base + OFF_QL);
    __half* khp = (__half*)(base + OFF_KH);
    __half* klp = (__half*)(base + OFF_KL);
    __half* vth = (__half*)(base + OFF_VTH);
    __half* vtl = (__half*)(base + OFF_VTL);
    __half* aoh = (__half*)(base + OFF_AOH);
    float* gqp = (float*)(base + OFF_QP);
    float* gkp = (float*)(base + OFF_KP);
    float2* cst = (float2*)(base + OFF_CS);

    cudaFuncSetAttribute(gemm2<0>,
                         cudaFuncAttributeMaxDynamicSharedMemorySize, GEMM_SMEM);
    cudaFuncSetAttribute(gemm2<1>,
                         cudaFuncAttributeMaxDynamicSharedMemorySize, GEMM_SMEM);
    cudaFuncSetAttribute(attn_mma,
                         cudaFuncAttributeMaxDynamicSharedMemorySize, ATTN_SMEM);

    rope_tab<<<TT, 64>>>(cst);
    ln_split<<<NTOK, 256>>>(x, lng, lnb, xnh, xnl);
    wsplit<<<4096, 256>>>(Wq, Wk, Wv, Wo, wh, wl);

    gemm2<0><<<dim3(24, NTOK/128), 256, GEMM_SMEM>>>(
        xnh, xnl, wh, wl, nullptr, qf, kf, vth, vtl);

    rope_kernel<<<BH*TT, 128>>>(qf, kf, hdr, cst, qhp, qlp, khp, klp, gqp, gkp);

    attn_mma<<<dim3(TT/128, BH), 256, ATTN_SMEM>>>(qhp, qlp, khp, klp, vth, vtl,
                                                   gqp, gkp, hsc, aoh);

    gemm2<1><<<dim3(8, NTOK/128), 256, GEMM_SMEM>>>(
        aoh, aoh, wh + 3*WPL, wl + 3*WPL, x, out, nullptr, nullptr, nullptr);
}

// round 14
// speedup vs baseline: 1.1986x; 1.0017x over previous
#include <cuda_runtime.h>
#include <cuda_fp16.h>
#include <math.h>

// Problem constants
#define BB 4
#define TT 2048
#define CC 1024
#define HH 8
#define DD 128
#define NTOK (BB*TT)          // 8192
#define BH   (BB*HH)          // 32
#define WPL  ((size_t)CC*CC)  // weight plane elems

// ---------------------------------------------------------------------------
// Scratch
// ---------------------------------------------------------------------------
#define SZ_F32 ((size_t)NTOK*CC*4)
#define SZ_BF  ((size_t)NTOK*CC*2)
#define SZ_WPL ((size_t)4*CC*CC*2)
#define SZ_P   ((size_t)BH*TT*4)
#define SZ_CS  ((size_t)TT*64*8)

#define OFF_XNH ((size_t)0)
#define OFF_XNL (OFF_XNH + SZ_BF)
#define OFF_WH  (OFF_XNL + SZ_BF)
#define OFF_WL  (OFF_WH + SZ_WPL)
#define OFF_QF  (OFF_WL + SZ_WPL)
#define OFF_KF  (OFF_QF + SZ_F32)
#define OFF_QH  (OFF_KF + SZ_F32)
#define OFF_QL  (OFF_QH + SZ_BF)
#define OFF_KH  (OFF_QL + SZ_BF)
#define OFF_KL  (OFF_KH + SZ_BF)
#define OFF_VTH (OFF_KL + SZ_BF)
#define OFF_VTL (OFF_VTH + SZ_BF)
#define OFF_AOH (OFF_VTL + SZ_BF)
#define OFF_QP  (OFF_AOH + SZ_BF)
#define OFF_KP  (OFF_QP + SZ_P)
#define OFF_CS  (OFF_KP + SZ_P)
#define SCRATCH_BYTES (OFF_CS + SZ_CS)

__device__ __align__(256) unsigned char g_scratch[SCRATCH_BYTES];

// ---------------------------------------------------------------------------
// helpers (fp16 MMA path)
// ---------------------------------------------------------------------------
__device__ __forceinline__ void mma_f16(float* c, const unsigned* a,
                                        unsigned b0, unsigned b1) {
    asm volatile(
        "mma.sync.aligned.m16n8k16.row.col.f32.f16.f16.f32 "
        "{%0,%1,%2,%3},{%4,%5,%6,%7},{%8,%9},{%0,%1,%2,%3};"
        : "+f"(c[0]), "+f"(c[1]), "+f"(c[2]), "+f"(c[3])
        : "r"(a[0]), "r"(a[1]), "r"(a[2]), "r"(a[3]), "r"(b0), "r"(b1));
}

__device__ __forceinline__ void ldsm_x4(unsigned r[4], unsigned addr) {
    asm volatile("ldmatrix.sync.aligned.m8n8.x4.shared.b16 {%0,%1,%2,%3}, [%4];"
        : "=r"(r[0]), "=r"(r[1]), "=r"(r[2]), "=r"(r[3]) : "r"(addr));
}

#define CP16(dst, src) \
    asm volatile("cp.async.cg.shared.global [%0], [%1], 16;" :: "r"(dst), "l"(src))
#define CP4(dst, src) \
    asm volatile("cp.async.ca.shared.global [%0], [%1], 4;" :: "r"(dst), "l"(src))
#define CP_COMMIT() asm volatile("cp.async.commit_group;")
#define CP_WAIT0()  asm volatile("cp.async.wait_group 0;")
#define CP_WAIT1()  asm volatile("cp.async.wait_group 1;")

// fp16 hi/lo split of two floats
__device__ __forceinline__ void split2(float a, float b, unsigned& hi, unsigned& lo) {
    __half2 h = __floats2half2_rn(a, b);
    float la = a - __half2float(__low2half(h));
    float lb = b - __half2float(__high2half(h));
    __half2 l = __floats2half2_rn(la, lb);
    hi = *(unsigned*)&h;
    lo = *(unsigned*)&l;
}

// plain fp16 pack of two floats
__device__ __forceinline__ unsigned pack2(float a, float b) {
    __half2 h = __floats2half2_rn(a, b);
    return *(unsigned*)&h;
}

// ---------------------------------------------------------------------------
// LayerNorm -> fp16 hi/lo planes
// ---------------------------------------------------------------------------
__global__ __launch_bounds__(256) void ln_split(
    const float* __restrict__ x, const float* __restrict__ gam,
    const float* __restrict__ bet,
    __half* __restrict__ xnh, __half* __restrict__ xnl)
{
    int row = blockIdx.x;
    int t   = threadIdx.x;
    const float4* xr = (const float4*)(x + (size_t)row * CC);
    float4 v = xr[t];
    float s  = v.x + v.y + v.z + v.w;
    float ss = v.x*v.x + v.y*v.y + v.z*v.z + v.w*v.w;
    #pragma unroll
    for (int o = 16; o; o >>= 1) {
        s  += __shfl_xor_sync(0xffffffffu, s,  o);
        ss += __shfl_xor_sync(0xffffffffu, ss, o);
    }
    __shared__ float ws[8], wss[8];
    int wid = t >> 5;
    if ((t & 31) == 0) { ws[wid] = s; wss[wid] = ss; }
    __syncthreads();
    s = 0.f; ss = 0.f;
    #pragma unroll
    for (int i = 0; i < 8; i++) { s += ws[i]; ss += wss[i]; }
    float mu  = s * (1.f / CC);
    float var = ss * (1.f / CC) - mu * mu;
    float inv = rsqrtf(var + 1e-5f);
    float4 g4 = ((const float4*)gam)[t];
    float4 b4 = ((const float4*)bet)[t];
    float4 o;
    o.x = (v.x - mu) * inv * g4.x + b4.x;
    o.y = (v.y - mu) * inv * g4.y + b4.y;
    o.z = (v.z - mu) * inv * g4.z + b4.z;
    o.w = (v.w - mu) * inv * g4.w + b4.w;
    unsigned h0, l0, h1, l1;
    split2(o.x, o.y, h0, l0);
    split2(o.z, o.w, h1, l1);
    size_t off = (size_t)row * CC + t*4;
    *(uint2*)&xnh[off] = make_uint2(h0, h1);
    *(uint2*)&xnl[off] = make_uint2(l0, l1);
}

// ---------------------------------------------------------------------------
// Split 4 weight matrices into fp16 hi/lo planes: plane order Wq,Wk,Wv,Wo
// ---------------------------------------------------------------------------
__global__ __launch_bounds__(256) void wsplit(
    const float* __restrict__ w0, const float* __restrict__ w1,
    const float* __restrict__ w2, const float* __restrict__ w3,
    __half* __restrict__ wh, __half* __restrict__ wl)
{
    int mid = blockIdx.x >> 10;
    const float* src = (mid == 0) ? w0 : (mid == 1) ? w1 : (mid == 2) ? w2 : w3;
    size_t idx = ((size_t)(blockIdx.x & 1023))*1024 + threadIdx.x*4;
    float4 v = *(const float4*)(src + idx);
    unsigned h0, l0, h1, l1;
    split2(v.x, v.y, h0, l0);
    split2(v.z, v.w, h1, l1);
    size_t off = (size_t)mid*WPL + idx;
    *(uint2*)&wh[off] = make_uint2(h0, h1);
    *(uint2*)&wl[off] = make_uint2(l0, l1);
}

// ---------------------------------------------------------------------------
// rope cos/sin table: cs[t*64+i] = (cos(t*inv_i), sin(t*inv_i))
// ---------------------------------------------------------------------------
__global__ __launch_bounds__(64) void rope_tab(float2* __restrict__ cs)
{
    int t = blockIdx.x, i = threadIdx.x;
    float inv = expf(-9.210340371976184f * (float)i * (1.f / 64.f));
    float sn, co;
    sincosf((float)t * inv, &sn, &co);
    cs[t*64 + i] = make_float2(co, sn);
}

// ---------------------------------------------------------------------------
// fp16 GEMM: cp.async double buffer + ldmatrix, 128x128x32, 2 CTA/SM.
// Terms: t1 = ah*bh, t2 = ah*bl, t3 = al*bh.
// MODE 0: QKV fused (grid.x=24; sel = x>>3): sel 0/1 (Q/K) -> 3 terms,
//         fp32 head-major out; sel 2 (V) -> 2 terms, transposed fp16
//         hi/lo planes [B,H,D,T]
// MODE 1: Wo, 2 terms, out0 = X + acc (fp32 row-major)
// ---------------------------------------------------------------------------
#define GSTR 40
#define GEMM_SMEM (4*2*128*GSTR*2)   // 81920 B

template<int MODE>
__global__ __launch_bounds__(256, 2) void gemm2(
    const __half* __restrict__ Ah, const __half* __restrict__ Al,
    const __half* __restrict__ Wh, const __half* __restrict__ Wl,
    const float* __restrict__ X,
    float* __restrict__ out0, float* __restrict__ out1,
    __half* __restrict__ oh, __half* __restrict__ ol)
{
    extern __shared__ __half smb[];
    __half* sAh = smb;
    __half* sAl = sAh + 2*128*GSTR;
    __half* sBh = sAl + 2*128*GSTR;
    __half* sBl = sBh + 2*128*GSTR;
    unsigned uAh = (unsigned)__cvta_generic_to_shared(sAh);
    unsigned uAl = (unsigned)__cvta_generic_to_shared(sAl);
    unsigned uBh = (unsigned)__cvta_generic_to_shared(sBh);
    unsigned uBl = (unsigned)__cvta_generic_to_shared(sBl);

    int tid = threadIdx.x, lane = tid & 31, warp = tid >> 5;
    int g = lane >> 2, tig = lane & 3;
    int wm = warp >> 1, wn = warp & 1;
    int sel = (MODE == 0) ? (blockIdx.x >> 3) : 0;
    int n0 = (MODE == 0) ? ((blockIdx.x & 7) << 7) : (blockIdx.x << 7);
    int m0 = blockIdx.y << 7;
    const __half* Wph = Wh + (size_t)sel*WPL;
    const __half* Wpl = Wl + (size_t)sel*WPL;
    bool term3 = (MODE == 0) && (sel < 2);

    int lr = tid >> 2;
    int lc8 = (tid & 3) * 8;

    float acc[16][4];
    #pragma unroll
    for (int i = 0; i < 16; i++)
        #pragma unroll
        for (int j = 0; j < 4; j++) acc[i][j] = 0.f;

    auto load_stage = [&](int buf, int k0) {
        size_t a0 = (size_t)(m0 + lr) * CC + k0 + lc8;
        size_t b0 = (size_t)(n0 + lr) * CC + k0 + lc8;
        unsigned d0 = (unsigned)(((buf*128 + lr)*GSTR + lc8) * 2);
        unsigned d1 = (unsigned)(((buf*128 + lr + 64)*GSTR + lc8) * 2);
        CP16(uAh + d0, Ah + a0);  CP16(uAh + d1, Ah + a0 + (size_t)64*CC);
        if (MODE == 0) {
            CP16(uAl + d0, Al + a0);  CP16(uAl + d1, Al + a0 + (size_t)64*CC);
        }
        CP16(uBh + d0, Wph + b0); CP16(uBh + d1, Wph + b0 + (size_t)64*CC);
        CP16(uBl + d0, Wpl + b0); CP16(uBl + d1, Wpl + b0 + (size_t)64*CC);
    };

    load_stage(0, 0);
    CP_COMMIT();
    CP_WAIT0();
    __syncthreads();

    int lra = ((lane >> 3) & 1) * 8 + (lane & 7);
    int lca = (lane >> 4) * 8;
    const int NIT = CC / 32;

    for (int it = 0; it < NIT; it++) {
        int buf = it & 1;
        if (it + 1 < NIT) { load_stage(buf ^ 1, (it + 1) * 32); CP_COMMIT(); }

        int sb = buf * 128;
        #pragma unroll
        for (int kk = 0; kk < 2; kk++) {
            int col = kk*16 + lca;
            unsigned ah[2][4], al2[2][4];
            #pragma unroll
            for (int mi = 0; mi < 2; mi++) {
                unsigned offA = (unsigned)(((sb + wm*32 + mi*16 + lra)*GSTR + col) * 2);
                ldsm_x4(ah[mi], uAh + offA);
                if (term3) ldsm_x4(al2[mi], uAl + offA);
            }
            #pragma unroll
            for (int np = 0; np < 2; np++) {
                unsigned b4h[2][4], b4l[2][4];
                #pragma unroll
                for (int u = 0; u < 2; u++) {
                    int ng = np*2 + u;
                    unsigned offB = (unsigned)(((sb + wn*64 + ng*16 + lra)*GSTR + col) * 2);
                    ldsm_x4(b4h[u], uBh + offB);
                    ldsm_x4(b4l[u], uBl + offB);
                }
                // term 1: ah x bh
                #pragma unroll
                for (int u = 0; u < 2; u++)
                    #pragma unroll
                    for (int hf = 0; hf < 2; hf++)
                        #pragma unroll
                        for (int mi = 0; mi < 2; mi++)
                            mma_f16(acc[mi*8 + (np*2+u)*2 + hf], ah[mi],
                                    b4h[u][hf], b4h[u][2 + hf]);
                // term 2: ah x bl
                #pragma unroll
                for (int u = 0; u < 2; u++)
                    #pragma unroll
                    for (int hf = 0; hf < 2; hf++)
                        #pragma unroll
                        for (int mi = 0; mi < 2; mi++)
                            mma_f16(acc[mi*8 + (np*2+u)*2 + hf], ah[mi],
                                    b4l[u][hf], b4l[u][2 + hf]);
                // term 3: al x bh (Q/K slices only)
                if (term3) {
                    #pragma unroll
                    for (int u = 0; u < 2; u++)
                        #pragma unroll
                        for (int hf = 0; hf < 2; hf++)
                            #pragma unroll
                            for (int mi = 0; mi < 2; mi++)
                                mma_f16(acc[mi*8 + (np*2+u)*2 + hf], al2[mi],
                                        b4h[u][hf], b4h[u][2 + hf]);
                }
            }
        }
        if (it + 1 < NIT) CP_WAIT0();
        __syncthreads();
    }

    // epilogue
    #pragma unroll
    for (int mi = 0; mi < 2; mi++) {
        #pragma unroll
        for (int ni = 0; ni < 8; ni++) {
            const float* c = acc[mi*8 + ni];
            int r0 = m0 + wm*32 + mi*16 + g;
            int c0 = n0 + wn*64 + ni*8 + 2*tig;
            #pragma unroll
            for (int half = 0; half < 2; half++) {
                int r = r0 + half*8;
                float v0 = c[half*2], v1 = c[half*2 + 1];
                if (MODE == 1) {
                    size_t o = (size_t)r * CC + c0;
                    float2 xv = *(const float2*)&X[o];
                    *(float2*)&out0[o] = make_float2(xv.x + v0, xv.y + v1);
                } else if (sel < 2) {
                    int b = r >> 11, t = r & 2047, h = c0 >> 7, d = c0 & 127;
                    float* outp = sel ? out1 : out0;
                    *(float2*)&outp[(((size_t)(b*HH + h) * TT) + t) * DD + d] =
                        make_float2(v0, v1);
                } else {
                    int b = r >> 11, t = r & 2047, h = c0 >> 7, d = c0 & 127;
                    size_t rb = ((size_t)((b*HH + h)*DD + d)) * TT + t;
                    __half h0 = __float2half_rn(v0);
                    __half h1 = __float2half_rn(v1);
                    oh[rb]      = h0;
                    ol[rb]      = __float2half_rn(v0 - __half2float(h0));
                    oh[rb + TT] = h1;
                    ol[rb + TT] = __float2half_rn(v1 - __half2float(h1));
                }
            }
        }
    }
}

// ---------------------------------------------------------------------------
// RoPE on q,k: read fp32 head-major, write fp16 hi/lo planes + qp/kp.
// Angles come from the precomputed cos/sin table.
// ---------------------------------------------------------------------------
__global__ __launch_bounds__(128) void rope_kernel(
    const float* __restrict__ qf, const float* __restrict__ kf,
    const float* __restrict__ dirs, const float2* __restrict__ cs,
    __half* __restrict__ qh, __half* __restrict__ ql,
    __half* __restrict__ kh, __half* __restrict__ kl,
    float* __restrict__ qp, float* __restrict__ kp)
{
    int idx = blockIdx.x;
    int t = idx & (TT - 1);
    int h = (idx >> 11) & (HH - 1);
    int tid = threadIdx.x;
    int i = tid & 63;
    bool isq = tid < 64;
    const float* src = (isq ? qf : kf) + (size_t)idx * DD;
    __half* dh = isq ? qh : kh;
    __half* dl = isq ? ql : kl;
    float x1 = src[i], x2 = src[i + 64];
    float2 cssn = cs[t*64 + i];
    float y1 = x1 * cssn.x - x2 * cssn.y;
    float y2 = x2 * cssn.x + x1 * cssn.y;
    size_t o = (size_t)idx * DD;
    __half h1 = __float2half_rn(y1);
    __half h2 = __float2half_rn(y2);
    dh[o + i]      = h1;
    dl[o + i]      = __float2half_rn(y1 - __half2float(h1));
    dh[o + i + 64] = h2;
    dl[o + i + 64] = __float2half_rn(y2 - __half2float(h2));
    __shared__ float red[6];
    if (i < 3) red[(tid >> 6) * 3 + i] = y1 * dirs[h * 3 + i];
    __syncthreads();
    if (tid == 0)  qp[idx] = red[0] + red[1] + red[2];
    if (tid == 64) kp[idx] = red[3] + red[4] + red[5];
}

// ---------------------------------------------------------------------------
// ONE-PASS dual-softmax flash attention, fp16 MMA.
// S: 3-term fp16 (score path). PV: 2-term (P_hi x (V_hi + V_lo)), both O & Og.
// Br=128 (256 thr, 8 warps, warp owns 16 rows), Bc=64.
// ---------------------------------------------------------------------------
#define KSTR 136
#define VSTR 72
#define Q_ELE (2*128*KSTR)
#define K_ELE (2*2*64*KSTR)
#define V_ELE (2*2*128*VSTR)
#define ATTN_SMEM ((Q_ELE + K_ELE + V_ELE)*2 + 2*64*4)
#define SCALE 0.08838834764831845f

__global__ __launch_bounds__(256, 1) void attn_mma(
    const __half* __restrict__ qh, const __half* __restrict__ ql,
    const __half* __restrict__ kh, const __half* __restrict__ kl,
    const __half* __restrict__ vth, const __half* __restrict__ vtl,
    const float* __restrict__ qp, const float* __restrict__ kp,
    const float* __restrict__ hsc,
    __half* __restrict__ aoh)
{
    extern __shared__ unsigned char sma[];
    __half* Qh = (__half*)sma;
    __half* Kb = Qh + Q_ELE;
    __half* Vb = Kb + K_ELE;
    float* kps = (float*)(Vb + V_ELE);

    unsigned uQ = (unsigned)__cvta_generic_to_shared(Qh);
    unsigned uK = (unsigned)__cvta_generic_to_shared(Kb);
    unsigned uV = (unsigned)__cvta_generic_to_shared(Vb);
    unsigned uKps = (unsigned)__cvta_generic_to_shared(kps);

    int bh = blockIdx.y;
    int b = bh >> 3, h = bh & 7;
    int q0 = (gridDim.x - 1 - blockIdx.x) << 7;
    size_t tb = (size_t)bh * TT;
    int tid = threadIdx.x;
    int lane = tid & 31, warp = tid >> 5;
    int g = lane >> 2, tig = lane & 3;
    int r0loc = warp*16 + g, r1loc = r0loc + 8;
    int lra = ((lane >> 3) & 1) * 8 + (lane & 7);
    int lca = (lane >> 4) * 8;

    {
        const __half* qhg = qh + (tb + q0) * DD;
        const __half* qlg = ql + (tb + q0) * DD;
        for (int i = tid; i < 2048; i += 256) {
            int r = i >> 4, c = (i & 15) << 3;
            *(uint4*)&Qh[r*KSTR + c]         = *(const uint4*)&qhg[r*DD + c];
            *(uint4*)&Qh[(128 + r)*KSTR + c] = *(const uint4*)&qlg[r*DD + c];
        }
    }
    float hs  = hsc[h];
    float qp0 = qp[tb + q0 + r0loc];
    float qp1 = qp[tb + q0 + r1loc];
    int ntiles = (q0 >> 6) + 2;

    auto prefetch = [&](int st, int n0) {
        const __half* khg = kh + (tb + n0) * DD;
        const __half* klg = kl + (tb + n0) * DD;
        for (int i = tid; i < 1024; i += 256) {
            int r = i >> 4, c = (i & 15) << 3;
            CP16(uK + (unsigned)(((st*128 + r)*KSTR + c) * 2),      khg + r*DD + c);
            CP16(uK + (unsigned)(((st*128 + 64 + r)*KSTR + c) * 2), klg + r*DD + c);
        }
        const __half* vhg = vth + (size_t)bh*DD*TT + n0;
        const __half* vlg = vtl + (size_t)bh*DD*TT + n0;
        for (int i = tid; i < 1024; i += 256) {
            int d = i >> 3, c = (i & 7) << 3;
            CP16(uV + (unsigned)(((st*256 + d)*VSTR + c) * 2),       vhg + (size_t)d*TT + c);
            CP16(uV + (unsigned)(((st*256 + 128 + d)*VSTR + c) * 2), vlg + (size_t)d*TT + c);
        }
        if (tid < 64) CP4(uKps + (unsigned)((st*64 + tid) * 4), kp + tb + n0 + tid);
    };

    float O[16][4], Og[16][4];
    #pragma unroll
    for (int i = 0; i < 16; i++)
        #pragma unroll
        for (int j = 0; j < 4; j++) { O[i][j] = 0.f; Og[i][j] = 0.f; }
    float l0 = 0.f, l1 = 0.f, lg0 = 0.f, lg1 = 0.f;

    prefetch(0, 0);
    CP_COMMIT();
    for (int it = 0; it < ntiles; it++) {
        int st = it & 1;
        int n0 = it << 6;
        if (it + 1 < ntiles) { prefetch(st ^ 1, (it + 1) << 6); CP_COMMIT(); CP_WAIT1(); }
        else                 { CP_WAIT0(); }
        __syncthreads();

        // ---- S = Q K^T (3-term fp16)
        float s[8][4];
        #pragma unroll
        for (int i = 0; i < 8; i++)
            #pragma unroll
            for (int j = 0; j < 4; j++) s[i][j] = 0.f;
        #pragma unroll
        for (int kk = 0; kk < 8; kk++) {
            int col = kk*16 + lca;
            unsigned qoff = (unsigned)(((warp*16 + lra)*KSTR + col) * 2);
            unsigned qa[4], qb[4];
            ldsm_x4(qa, uQ + qoff);
            ldsm_x4(qb, uQ + qoff + (unsigned)(128*KSTR*2));
            #pragma unroll
            for (int np = 0; np < 2; np++) {
                unsigned kh4[2][4], kl4[2][4];
                #pragma unroll
                for (int u = 0; u < 2; u++) {
                    int ng = np*2 + u;
                    unsigned koff = (unsigned)(((st*128 + ng*16 + lra)*KSTR + col) * 2);
                    ldsm_x4(kh4[u], uK + koff);
                    ldsm_x4(kl4[u], uK + koff + (unsigned)(64*KSTR*2));
                }
                #pragma unroll
                for (int u = 0; u < 2; u++)
                    #pragma unroll
                    for (int hf = 0; hf < 2; hf++)
                        mma_f16(s[(np*2+u)*2 + hf], qa, kh4[u][hf], kh4[u][2 + hf]);
                #pragma unroll
                for (int u = 0; u < 2; u++)
                    #pragma unroll
                    for (int hf = 0; hf < 2; hf++)
                        mma_f16(s[(np*2+u)*2 + hf], qa, kl4[u][hf], kl4[u][2 + hf]);
                #pragma unroll
                for (int u = 0; u < 2; u++)
                    #pragma unroll
                    for (int hf = 0; hf < 2; hf++)
                        mma_f16(s[(np*2+u)*2 + hf], qb, kh4[u][hf], kh4[u][2 + hf]);
            }
        }

        int relq = q0 - n0;
        #pragma unroll
        for (int ni = 0; ni < 8; ni++) {
            #pragma unroll
            for (int j = 0; j < 4; j++) {
                int cl = ni*8 + 2*tig + (j & 1);
                int rl = (j < 2) ? r0loc : r1loc;
                bool ok = (cl - rl <= relq);
                float e = ok ? __expf(s[ni][j] * SCALE) : 0.f;
                s[ni][j] = e;
                if (j < 2) l0 += e; else l1 += e;
            }
        }

        const float* kpst = kps + st*64;
        #pragma unroll
        for (int kc = 0; kc < 4; kc++) {
            unsigned ph[4], gh[4];
            ph[0] = pack2(s[2*kc][0],   s[2*kc][1]);
            ph[1] = pack2(s[2*kc][2],   s[2*kc][3]);
            ph[2] = pack2(s[2*kc+1][0], s[2*kc+1][1]);
            ph[3] = pack2(s[2*kc+1][2], s[2*kc+1][3]);
            {
                int c0 = kc*16 + 2*tig;
                float k0v = kpst[c0],     k1v = kpst[c0 + 1];
                float k8v = kpst[c0 + 8], k9v = kpst[c0 + 9];
                float ge00 = (c0     - r0loc <= relq) ? __expf(qp0 * k0v) : 0.f;
                float ge01 = (c0 + 1 - r0loc <= relq) ? __expf(qp0 * k1v) : 0.f;
                float ge10 = (c0     - r1loc <= relq) ? __expf(qp1 * k0v) : 0.f;
                float ge11 = (c0 + 1 - r1loc <= relq) ? __expf(qp1 * k1v) : 0.f;
                float ge08 = (c0 + 8 - r0loc <= relq) ? __expf(qp0 * k8v) : 0.f;
                float ge09 = (c0 + 9 - r0loc <= relq) ? __expf(qp0 * k9v) : 0.f;
                float ge18 = (c0 + 8 - r1loc <= relq) ? __expf(qp1 * k8v) : 0.f;
                float ge19 = (c0 + 9 - r1loc <= relq) ? __expf(qp1 * k9v) : 0.f;
                lg0 += ge00 + ge01 + ge08 + ge09;
                lg1 += ge10 + ge11 + ge18 + ge19;
                gh[0] = pack2(ge00, ge01);
                gh[1] = pack2(ge10, ge11);
                gh[2] = pack2(ge08, ge09);
                gh[3] = pack2(ge18, ge19);
            }
            // PV: 2-term (P_hi x V_hi + P_hi x V_lo) for both O and Og
            #pragma unroll
            for (int ndg = 0; ndg < 8; ndg++) {
                unsigned voff = (unsigned)(((st*256 + ndg*16 + lra)*VSTR + kc*16 + lca) * 2);
                unsigned vh4[4], vl4[4];
                ldsm_x4(vh4, uV + voff);
                ldsm_x4(vl4, uV + voff + (unsigned)(128*VSTR*2));
                int nd0 = ndg*2, nd1 = ndg*2 + 1;
                mma_f16(O[nd0],  ph, vh4[0], vh4[2]);
                mma_f16(O[nd1],  ph, vh4[1], vh4[3]);
                mma_f16(Og[nd0], gh, vh4[0], vh4[2]);
                mma_f16(Og[nd1], gh, vh4[1], vh4[3]);
                mma_f16(O[nd0],  ph, vl4[0], vl4[2]);
                mma_f16(O[nd1],  ph, vl4[1], vl4[3]);
                mma_f16(Og[nd0], gh, vl4[0], vl4[2]);
                mma_f16(Og[nd1], gh, vl4[1], vl4[3]);
            }
        }
        __syncthreads();
    }

    #pragma unroll
    for (int o = 1; o <= 2; o <<= 1) {
        l0  += __shfl_xor_sync(0xffffffffu, l0,  o);
        l1  += __shfl_xor_sync(0xffffffffu, l1,  o);
        lg0 += __shfl_xor_sync(0xffffffffu, lg0, o);
        lg1 += __shfl_xor_sync(0xffffffffu, lg1, o);
    }
    float c1a = (1.f - hs) / l0, c2a = hs / lg0;
    float c1b = (1.f - hs) / l1, c2b = hs / lg1;

    // epilogue: fp16 plane for Wo GEMM (Wo uses 2-term, A-lo not needed)
    size_t orow0 = (size_t)(b*TT + q0 + r0loc) * CC + h*DD;
    size_t orow1 = (size_t)(b*TT + q0 + r1loc) * CC + h*DD;
    #pragma unroll
    for (int nd = 0; nd < 16; nd++) {
        int d0 = nd*8 + 2*tig;
        float v0 = c1a*O[nd][0] + c2a*Og[nd][0];
        float v1 = c1a*O[nd][1] + c2a*Og[nd][1];
        *(unsigned*)&aoh[orow0 + d0] = pack2(v0, v1);
        v0 = c1b*O[nd][2] + c2b*Og[nd][2];
        v1 = c1b*O[nd][3] + c2b*Og[nd][3];
        *(unsigned*)&aoh[orow1 + d0] = pack2(v0, v1);
    }
}

// ---------------------------------------------------------------------------
// Launcher
// ---------------------------------------------------------------------------
extern "C" void kernel_launch(void* const* d_in, const int* in_sizes, int n_in,
                              void* d_out, int out_size)
{
    const float* x   = (const float*)d_in[0];
    const float* Wq  = (const float*)d_in[1];
    const float* Wk  = (const float*)d_in[2];
    const float* Wv  = (const float*)d_in[3];
    const float* Wo  = (const float*)d_in[4];
    const float* lng = (const float*)d_in[5];
    const float* lnb = (const float*)d_in[6];
    const float* hsc = (const float*)d_in[7];
    const float* hdr = (const float*)d_in[8];
    float* out = (float*)d_out;

    unsigned char* base = nullptr;
    cudaGetSymbolAddress((void**)&base, g_scratch);
    __half* xnh = (__half*)(base + OFF_XNH);
    __half* xnl = (__half*)(base + OFF_XNL);
    __half* wh  = (__half*)(base + OFF_WH);
    __half* wl  = (__half*)(base + OFF_WL);
    float* qf = (float*)(base + OFF_QF);
    float* kf = (float*)(base + OFF_KF);
    __half* qhp = (__half*)(base + OFF_QH);
    __half* qlp = (__half*)(base + OFF_QL);
    __half* khp = (__half*)(base + OFF_KH);
    __half* klp = (__half*)(base + OFF_KL);
    __half* vth = (__half*)(base + OFF_VTH);
    __half* vtl = (__half*)(base + OFF_VTL);
    __half* aoh = (__half*)(base + OFF_AOH);
    float* gqp = (float*)(base + OFF_QP);
    float* gkp = (float*)(base + OFF_KP);
    float2* cst = (float2*)(base + OFF_CS);

    cudaFuncSetAttribute(gemm2<0>,
                         cudaFuncAttributeMaxDynamicSharedMemorySize, GEMM_SMEM);
    cudaFuncSetAttribute(gemm2<1>,
                         cudaFuncAttributeMaxDynamicSharedMemorySize, GEMM_SMEM);
    cudaFuncSetAttribute(attn_mma,
                         cudaFuncAttributeMaxDynamicSharedMemorySize, ATTN_SMEM);

    rope_tab<<<TT, 64>>>(cst);
    ln_split<<<NTOK, 256>>>(x, lng, lnb, xnh, xnl);
    wsplit<<<4096, 256>>>(Wq, Wk, Wv, Wo, wh, wl);

    gemm2<0><<<dim3(24, NTOK/128), 256, GEMM_SMEM>>>(
        xnh, xnl, wh, wl, nullptr, qf, kf, vth, vtl);

    rope_kernel<<<BH*TT, 128>>>(qf, kf, hdr, cst, qhp, qlp, khp, klp, gqp, gkp);

    attn_mma<<<dim3(TT/128, BH), 256, ATTN_SMEM>>>(qhp, qlp, khp, klp, vth, vtl,
                                                   gqp, gkp, hsc, aoh);

    gemm2<1><<<dim3(8, NTOK/128), 256, GEMM_SMEM>>>(
        aoh, aoh, wh + 3*WPL, wl + 3*WPL, x, out, nullptr, nullptr, nullptr);
}

// round 15
// speedup vs baseline: 1.2948x; 1.0803x over previous
#include <cuda_runtime.h>
#include <cuda_fp16.h>
#include <math.h>

// Problem constants
#define BB 4
#define TT 2048
#define CC 1024
#define HH 8
#define DD 128
#define NTOK (BB*TT)          // 8192
#define BH   (BB*HH)          // 32
#define WPL  ((size_t)CC*CC)  // weight plane elems

// ---------------------------------------------------------------------------
// Scratch
// ---------------------------------------------------------------------------
#define SZ_F32 ((size_t)NTOK*CC*4)
#define SZ_BF  ((size_t)NTOK*CC*2)
#define SZ_WPL ((size_t)4*CC*CC*2)
#define SZ_P   ((size_t)BH*TT*4)
#define SZ_CS  ((size_t)TT*64*8)

#define OFF_XNH ((size_t)0)
#define OFF_XNL (OFF_XNH + SZ_BF)
#define OFF_WH  (OFF_XNL + SZ_BF)
#define OFF_WL  (OFF_WH + SZ_WPL)
#define OFF_QF  (OFF_WL + SZ_WPL)
#define OFF_KF  (OFF_QF + SZ_F32)
#define OFF_QH  (OFF_KF + SZ_F32)
#define OFF_KH  (OFF_QH + SZ_BF)
#define OFF_KL  (OFF_KH + SZ_BF)
#define OFF_VTH (OFF_KL + SZ_BF)
#define OFF_VTL (OFF_VTH + SZ_BF)
#define OFF_AOH (OFF_VTL + SZ_BF)
#define OFF_QP  (OFF_AOH + SZ_BF)
#define OFF_KP  (OFF_QP + SZ_P)
#define OFF_CS  (OFF_KP + SZ_P)
#define SCRATCH_BYTES (OFF_CS + SZ_CS)

__device__ __align__(256) unsigned char g_scratch[SCRATCH_BYTES];

// ---------------------------------------------------------------------------
// helpers (fp16 MMA path)
// ---------------------------------------------------------------------------
__device__ __forceinline__ void mma_f16(float* c, const unsigned* a,
                                        unsigned b0, unsigned b1) {
    asm volatile(
        "mma.sync.aligned.m16n8k16.row.col.f32.f16.f16.f32 "
        "{%0,%1,%2,%3},{%4,%5,%6,%7},{%8,%9},{%0,%1,%2,%3};"
        : "+f"(c[0]), "+f"(c[1]), "+f"(c[2]), "+f"(c[3])
        : "r"(a[0]), "r"(a[1]), "r"(a[2]), "r"(a[3]), "r"(b0), "r"(b1));
}

__device__ __forceinline__ void ldsm_x4(unsigned r[4], unsigned addr) {
    asm volatile("ldmatrix.sync.aligned.m8n8.x4.shared.b16 {%0,%1,%2,%3}, [%4];"
        : "=r"(r[0]), "=r"(r[1]), "=r"(r[2]), "=r"(r[3]) : "r"(addr));
}

#define CP16(dst, src) \
    asm volatile("cp.async.cg.shared.global [%0], [%1], 16;" :: "r"(dst), "l"(src))
#define CP4(dst, src) \
    asm volatile("cp.async.ca.shared.global [%0], [%1], 4;" :: "r"(dst), "l"(src))
#define CP_COMMIT() asm volatile("cp.async.commit_group;")
#define CP_WAIT0()  asm volatile("cp.async.wait_group 0;")
#define CP_WAIT1()  asm volatile("cp.async.wait_group 1;")

// fp16 hi/lo split of two floats
__device__ __forceinline__ void split2(float a, float b, unsigned& hi, unsigned& lo) {
    __half2 h = __floats2half2_rn(a, b);
    float la = a - __half2float(__low2half(h));
    float lb = b - __half2float(__high2half(h));
    __half2 l = __floats2half2_rn(la, lb);
    hi = *(unsigned*)&h;
    lo = *(unsigned*)&l;
}

// plain fp16 pack of two floats
__device__ __forceinline__ unsigned pack2(float a, float b) {
    __half2 h = __floats2half2_rn(a, b);
    return *(unsigned*)&h;
}

// ---------------------------------------------------------------------------
// LayerNorm -> fp16 hi/lo planes
// ---------------------------------------------------------------------------
__global__ __launch_bounds__(256) void ln_split(
    const float* __restrict__ x, const float* __restrict__ gam,
    const float* __restrict__ bet,
    __half* __restrict__ xnh, __half* __restrict__ xnl)
{
    int row = blockIdx.x;
    int t   = threadIdx.x;
    const float4* xr = (const float4*)(x + (size_t)row * CC);
    float4 v = xr[t];
    float s  = v.x + v.y + v.z + v.w;
    float ss = v.x*v.x + v.y*v.y + v.z*v.z + v.w*v.w;
    #pragma unroll
    for (int o = 16; o; o >>= 1) {
        s  += __shfl_xor_sync(0xffffffffu, s,  o);
        ss += __shfl_xor_sync(0xffffffffu, ss, o);
    }
    __shared__ float ws[8], wss[8];
    int wid = t >> 5;
    if ((t & 31) == 0) { ws[wid] = s; wss[wid] = ss; }
    __syncthreads();
    s = 0.f; ss = 0.f;
    #pragma unroll
    for (int i = 0; i < 8; i++) { s += ws[i]; ss += wss[i]; }
    float mu  = s * (1.f / CC);
    float var = ss * (1.f / CC) - mu * mu;
    float inv = rsqrtf(var + 1e-5f);
    float4 g4 = ((const float4*)gam)[t];
    float4 b4 = ((const float4*)bet)[t];
    float4 o;
    o.x = (v.x - mu) * inv * g4.x + b4.x;
    o.y = (v.y - mu) * inv * g4.y + b4.y;
    o.z = (v.z - mu) * inv * g4.z + b4.z;
    o.w = (v.w - mu) * inv * g4.w + b4.w;
    unsigned h0, l0, h1, l1;
    split2(o.x, o.y, h0, l0);
    split2(o.z, o.w, h1, l1);
    size_t off = (size_t)row * CC + t*4;
    *(uint2*)&xnh[off] = make_uint2(h0, h1);
    *(uint2*)&xnl[off] = make_uint2(l0, l1);
}

// ---------------------------------------------------------------------------
// Split 4 weight matrices into fp16 hi/lo planes: plane order Wq,Wk,Wv,Wo
// ---------------------------------------------------------------------------
__global__ __launch_bounds__(256) void wsplit(
    const float* __restrict__ w0, const float* __restrict__ w1,
    const float* __restrict__ w2, const float* __restrict__ w3,
    __half* __restrict__ wh, __half* __restrict__ wl)
{
    int mid = blockIdx.x >> 10;
    const float* src = (mid == 0) ? w0 : (mid == 1) ? w1 : (mid == 2) ? w2 : w3;
    size_t idx = ((size_t)(blockIdx.x & 1023))*1024 + threadIdx.x*4;
    float4 v = *(const float4*)(src + idx);
    unsigned h0, l0, h1, l1;
    split2(v.x, v.y, h0, l0);
    split2(v.z, v.w, h1, l1);
    size_t off = (size_t)mid*WPL + idx;
    *(uint2*)&wh[off] = make_uint2(h0, h1);
    *(uint2*)&wl[off] = make_uint2(l0, l1);
}

// ---------------------------------------------------------------------------
// rope cos/sin table: cs[t*64+i] = (cos(t*inv_i), sin(t*inv_i))
// ---------------------------------------------------------------------------
__global__ __launch_bounds__(64) void rope_tab(float2* __restrict__ cs)
{
    int t = blockIdx.x, i = threadIdx.x;
    float inv = expf(-9.210340371976184f * (float)i * (1.f / 64.f));
    float sn, co;
    sincosf((float)t * inv, &sn, &co);
    cs[t*64 + i] = make_float2(co, sn);
}

// ---------------------------------------------------------------------------
// fp16 GEMM: cp.async double buffer + ldmatrix, 128x128x32, 2 CTA/SM.
// Terms: t1 = ah*bh, t2 = ah*bl, t3 = al*bh.
// MODE 0: QKV fused (grid.x=24; sel = x>>3): sel 0/1 (Q/K) -> 3 terms,
//         fp32 head-major out; sel 2 (V) -> 2 terms, transposed fp16
//         hi/lo planes [B,H,D,T]
// MODE 1: Wo, 2 terms, out0 = X + acc (fp32 row-major)
// ---------------------------------------------------------------------------
#define GSTR 40
#define GEMM_SMEM (4*2*128*GSTR*2)   // 81920 B

template<int MODE>
__global__ __launch_bounds__(256, 2) void gemm2(
    const __half* __restrict__ Ah, const __half* __restrict__ Al,
    const __half* __restrict__ Wh, const __half* __restrict__ Wl,
    const float* __restrict__ X,
    float* __restrict__ out0, float* __restrict__ out1,
    __half* __restrict__ oh, __half* __restrict__ ol)
{
    extern __shared__ __half smb[];
    __half* sAh = smb;
    __half* sAl = sAh + 2*128*GSTR;
    __half* sBh = sAl + 2*128*GSTR;
    __half* sBl = sBh + 2*128*GSTR;
    unsigned uAh = (unsigned)__cvta_generic_to_shared(sAh);
    unsigned uAl = (unsigned)__cvta_generic_to_shared(sAl);
    unsigned uBh = (unsigned)__cvta_generic_to_shared(sBh);
    unsigned uBl = (unsigned)__cvta_generic_to_shared(sBl);

    int tid = threadIdx.x, lane = tid & 31, warp = tid >> 5;
    int g = lane >> 2, tig = lane & 3;
    int wm = warp >> 1, wn = warp & 1;
    int sel = (MODE == 0) ? (blockIdx.x >> 3) : 0;
    int n0 = (MODE == 0) ? ((blockIdx.x & 7) << 7) : (blockIdx.x << 7);
    int m0 = blockIdx.y << 7;
    const __half* Wph = Wh + (size_t)sel*WPL;
    const __half* Wpl = Wl + (size_t)sel*WPL;
    bool term3 = (MODE == 0) && (sel < 2);

    int lr = tid >> 2;
    int lc8 = (tid & 3) * 8;

    float acc[16][4];
    #pragma unroll
    for (int i = 0; i < 16; i++)
        #pragma unroll
        for (int j = 0; j < 4; j++) acc[i][j] = 0.f;

    auto load_stage = [&](int buf, int k0) {
        size_t a0 = (size_t)(m0 + lr) * CC + k0 + lc8;
        size_t b0 = (size_t)(n0 + lr) * CC + k0 + lc8;
        unsigned d0 = (unsigned)(((buf*128 + lr)*GSTR + lc8) * 2);
        unsigned d1 = (unsigned)(((buf*128 + lr + 64)*GSTR + lc8) * 2);
        CP16(uAh + d0, Ah + a0);  CP16(uAh + d1, Ah + a0 + (size_t)64*CC);
        if (MODE == 0) {
            CP16(uAl + d0, Al + a0);  CP16(uAl + d1, Al + a0 + (size_t)64*CC);
        }
        CP16(uBh + d0, Wph + b0); CP16(uBh + d1, Wph + b0 + (size_t)64*CC);
        CP16(uBl + d0, Wpl + b0); CP16(uBl + d1, Wpl + b0 + (size_t)64*CC);
    };

    load_stage(0, 0);
    CP_COMMIT();
    CP_WAIT0();
    __syncthreads();

    int lra = ((lane >> 3) & 1) * 8 + (lane & 7);
    int lca = (lane >> 4) * 8;
    const int NIT = CC / 32;

    for (int it = 0; it < NIT; it++) {
        int buf = it & 1;
        if (it + 1 < NIT) { load_stage(buf ^ 1, (it + 1) * 32); CP_COMMIT(); }

        int sb = buf * 128;
        #pragma unroll
        for (int kk = 0; kk < 2; kk++) {
            int col = kk*16 + lca;
            unsigned ah[2][4], al2[2][4];
            #pragma unroll
            for (int mi = 0; mi < 2; mi++) {
                unsigned offA = (unsigned)(((sb + wm*32 + mi*16 + lra)*GSTR + col) * 2);
                ldsm_x4(ah[mi], uAh + offA);
                if (term3) ldsm_x4(al2[mi], uAl + offA);
            }
            #pragma unroll
            for (int np = 0; np < 2; np++) {
                unsigned b4h[2][4], b4l[2][4];
                #pragma unroll
                for (int u = 0; u < 2; u++) {
                    int ng = np*2 + u;
                    unsigned offB = (unsigned)(((sb + wn*64 + ng*16 + lra)*GSTR + col) * 2);
                    ldsm_x4(b4h[u], uBh + offB);
                    ldsm_x4(b4l[u], uBl + offB);
                }
                // term 1: ah x bh
                #pragma unroll
                for (int u = 0; u < 2; u++)
                    #pragma unroll
                    for (int hf = 0; hf < 2; hf++)
                        #pragma unroll
                        for (int mi = 0; mi < 2; mi++)
                            mma_f16(acc[mi*8 + (np*2+u)*2 + hf], ah[mi],
                                    b4h[u][hf], b4h[u][2 + hf]);
                // term 2: ah x bl
                #pragma unroll
                for (int u = 0; u < 2; u++)
                    #pragma unroll
                    for (int hf = 0; hf < 2; hf++)
                        #pragma unroll
                        for (int mi = 0; mi < 2; mi++)
                            mma_f16(acc[mi*8 + (np*2+u)*2 + hf], ah[mi],
                                    b4l[u][hf], b4l[u][2 + hf]);
                // term 3: al x bh (Q/K slices only)
                if (term3) {
                    #pragma unroll
                    for (int u = 0; u < 2; u++)
                        #pragma unroll
                        for (int hf = 0; hf < 2; hf++)
                            #pragma unroll
                            for (int mi = 0; mi < 2; mi++)
                                mma_f16(acc[mi*8 + (np*2+u)*2 + hf], al2[mi],
                                        b4h[u][hf], b4h[u][2 + hf]);
                }
            }
        }
        if (it + 1 < NIT) CP_WAIT0();
        __syncthreads();
    }

    // epilogue
    #pragma unroll
    for (int mi = 0; mi < 2; mi++) {
        #pragma unroll
        for (int ni = 0; ni < 8; ni++) {
            const float* c = acc[mi*8 + ni];
            int r0 = m0 + wm*32 + mi*16 + g;
            int c0 = n0 + wn*64 + ni*8 + 2*tig;
            #pragma unroll
            for (int half = 0; half < 2; half++) {
                int r = r0 + half*8;
                float v0 = c[half*2], v1 = c[half*2 + 1];
                if (MODE == 1) {
                    size_t o = (size_t)r * CC + c0;
                    float2 xv = *(const float2*)&X[o];
                    *(float2*)&out0[o] = make_float2(xv.x + v0, xv.y + v1);
                } else if (sel < 2) {
                    int b = r >> 11, t = r & 2047, h = c0 >> 7, d = c0 & 127;
                    float* outp = sel ? out1 : out0;
                    *(float2*)&outp[(((size_t)(b*HH + h) * TT) + t) * DD + d] =
                        make_float2(v0, v1);
                } else {
                    int b = r >> 11, t = r & 2047, h = c0 >> 7, d = c0 & 127;
                    size_t rb = ((size_t)((b*HH + h)*DD + d)) * TT + t;
                    __half h0 = __float2half_rn(v0);
                    __half h1 = __float2half_rn(v1);
                    oh[rb]      = h0;
                    ol[rb]      = __float2half_rn(v0 - __half2float(h0));
                    oh[rb + TT] = h1;
                    ol[rb + TT] = __float2half_rn(v1 - __half2float(h1));
                }
            }
        }
    }
}

// ---------------------------------------------------------------------------
// RoPE on q,k: read fp32 head-major, write fp16 planes + qp/kp.
// Q gets hi plane only (S-GEMM is 2-term); K gets hi+lo planes.
// ---------------------------------------------------------------------------
__global__ __launch_bounds__(128) void rope_kernel(
    const float* __restrict__ qf, const float* __restrict__ kf,
    const float* __restrict__ dirs, const float2* __restrict__ cs,
    __half* __restrict__ qh,
    __half* __restrict__ kh, __half* __restrict__ kl,
    float* __restrict__ qp, float* __restrict__ kp)
{
    int idx = blockIdx.x;
    int t = idx & (TT - 1);
    int h = (idx >> 11) & (HH - 1);
    int tid = threadIdx.x;
    int i = tid & 63;
    bool isq = tid < 64;
    const float* src = (isq ? qf : kf) + (size_t)idx * DD;
    float x1 = src[i], x2 = src[i + 64];
    float2 cssn = cs[t*64 + i];
    float y1 = x1 * cssn.x - x2 * cssn.y;
    float y2 = x2 * cssn.x + x1 * cssn.y;
    size_t o = (size_t)idx * DD;
    __half h1 = __float2half_rn(y1);
    __half h2 = __float2half_rn(y2);
    if (isq) {
        qh[o + i]      = h1;
        qh[o + i + 64] = h2;
    } else {
        kh[o + i]      = h1;
        kl[o + i]      = __float2half_rn(y1 - __half2float(h1));
        kh[o + i + 64] = h2;
        kl[o + i + 64] = __float2half_rn(y2 - __half2float(h2));
    }
    __shared__ float red[6];
    if (i < 3) red[(tid >> 6) * 3 + i] = y1 * dirs[h * 3 + i];
    __syncthreads();
    if (tid == 0)  qp[idx] = red[0] + red[1] + red[2];
    if (tid == 64) kp[idx] = red[3] + red[4] + red[5];
}

// ---------------------------------------------------------------------------
// ONE-PASS dual-softmax flash attention, fp16 MMA.
// S: 2-term (qh x (kh + kl)). O PV: 2-term (ph x (vh + vl)). Og PV: 1-term.
// Br=128 (256 thr, 8 warps, warp owns 16 rows), Bc=64.
// ---------------------------------------------------------------------------
#define KSTR 136
#define VSTR 72
#define Q_ELE (128*KSTR)
#define K_ELE (2*2*64*KSTR)
#define V_ELE (2*2*128*VSTR)
#define ATTN_SMEM ((Q_ELE + K_ELE + V_ELE)*2 + 2*64*4)
#define SCALE 0.08838834764831845f

__global__ __launch_bounds__(256, 1) void attn_mma(
    const __half* __restrict__ qh,
    const __half* __restrict__ kh, const __half* __restrict__ kl,
    const __half* __restrict__ vth, const __half* __restrict__ vtl,
    const float* __restrict__ qp, const float* __restrict__ kp,
    const float* __restrict__ hsc,
    __half* __restrict__ aoh)
{
    extern __shared__ unsigned char sma[];
    __half* Qh = (__half*)sma;
    __half* Kb = Qh + Q_ELE;
    __half* Vb = Kb + K_ELE;
    float* kps = (float*)(Vb + V_ELE);

    unsigned uQ = (unsigned)__cvta_generic_to_shared(Qh);
    unsigned uK = (unsigned)__cvta_generic_to_shared(Kb);
    unsigned uV = (unsigned)__cvta_generic_to_shared(Vb);
    unsigned uKps = (unsigned)__cvta_generic_to_shared(kps);

    int bh = blockIdx.y;
    int b = bh >> 3, h = bh & 7;
    int q0 = (gridDim.x - 1 - blockIdx.x) << 7;
    size_t tb = (size_t)bh * TT;
    int tid = threadIdx.x;
    int lane = tid & 31, warp = tid >> 5;
    int g = lane >> 2, tig = lane & 3;
    int r0loc = warp*16 + g, r1loc = r0loc + 8;
    int lra = ((lane >> 3) & 1) * 8 + (lane & 7);
    int lca = (lane >> 4) * 8;

    {
        const __half* qhg = qh + (tb + q0) * DD;
        for (int i = tid; i < 2048; i += 256) {
            int r = i >> 4, c = (i & 15) << 3;
            *(uint4*)&Qh[r*KSTR + c] = *(const uint4*)&qhg[r*DD + c];
        }
    }
    float hs  = hsc[h];
    float qp0 = qp[tb + q0 + r0loc];
    float qp1 = qp[tb + q0 + r1loc];
    int ntiles = (q0 >> 6) + 2;

    auto prefetch = [&](int st, int n0) {
        const __half* khg = kh + (tb + n0) * DD;
        const __half* klg = kl + (tb + n0) * DD;
        for (int i = tid; i < 1024; i += 256) {
            int r = i >> 4, c = (i & 15) << 3;
            CP16(uK + (unsigned)(((st*128 + r)*KSTR + c) * 2),      khg + r*DD + c);
            CP16(uK + (unsigned)(((st*128 + 64 + r)*KSTR + c) * 2), klg + r*DD + c);
        }
        const __half* vhg = vth + (size_t)bh*DD*TT + n0;
        const __half* vlg = vtl + (size_t)bh*DD*TT + n0;
        for (int i = tid; i < 1024; i += 256) {
            int d = i >> 3, c = (i & 7) << 3;
            CP16(uV + (unsigned)(((st*256 + d)*VSTR + c) * 2),       vhg + (size_t)d*TT + c);
            CP16(uV + (unsigned)(((st*256 + 128 + d)*VSTR + c) * 2), vlg + (size_t)d*TT + c);
        }
        if (tid < 64) CP4(uKps + (unsigned)((st*64 + tid) * 4), kp + tb + n0 + tid);
    };

    float O[16][4], Og[16][4];
    #pragma unroll
    for (int i = 0; i < 16; i++)
        #pragma unroll
        for (int j = 0; j < 4; j++) { O[i][j] = 0.f; Og[i][j] = 0.f; }
    float l0 = 0.f, l1 = 0.f, lg0 = 0.f, lg1 = 0.f;

    prefetch(0, 0);
    CP_COMMIT();
    for (int it = 0; it < ntiles; it++) {
        int st = it & 1;
        int n0 = it << 6;
        if (it + 1 < ntiles) { prefetch(st ^ 1, (it + 1) << 6); CP_COMMIT(); CP_WAIT1(); }
        else                 { CP_WAIT0(); }
        __syncthreads();

        // ---- S = Q K^T (2-term fp16: qh x kh + qh x kl)
        float s[8][4];
        #pragma unroll
        for (int i = 0; i < 8; i++)
            #pragma unroll
            for (int j = 0; j < 4; j++) s[i][j] = 0.f;
        #pragma unroll
        for (int kk = 0; kk < 8; kk++) {
            int col = kk*16 + lca;
            unsigned qoff = (unsigned)(((warp*16 + lra)*KSTR + col) * 2);
            unsigned qa[4];
            ldsm_x4(qa, uQ + qoff);
            #pragma unroll
            for (int np = 0; np < 2; np++) {
                unsigned kh4[2][4], kl4[2][4];
                #pragma unroll
                for (int u = 0; u < 2; u++) {
                    int ng = np*2 + u;
                    unsigned koff = (unsigned)(((st*128 + ng*16 + lra)*KSTR + col) * 2);
                    ldsm_x4(kh4[u], uK + koff);
                    ldsm_x4(kl4[u], uK + koff + (unsigned)(64*KSTR*2));
                }
                #pragma unroll
                for (int u = 0; u < 2; u++)
                    #pragma unroll
                    for (int hf = 0; hf < 2; hf++)
                        mma_f16(s[(np*2+u)*2 + hf], qa, kh4[u][hf], kh4[u][2 + hf]);
                #pragma unroll
                for (int u = 0; u < 2; u++)
                    #pragma unroll
                    for (int hf = 0; hf < 2; hf++)
                        mma_f16(s[(np*2+u)*2 + hf], qa, kl4[u][hf], kl4[u][2 + hf]);
            }
        }

        int relq = q0 - n0;
        #pragma unroll
        for (int ni = 0; ni < 8; ni++) {
            #pragma unroll
            for (int j = 0; j < 4; j++) {
                int cl = ni*8 + 2*tig + (j & 1);
                int rl = (j < 2) ? r0loc : r1loc;
                bool ok = (cl - rl <= relq);
                float e = ok ? __expf(s[ni][j] * SCALE) : 0.f;
                s[ni][j] = e;
                if (j < 2) l0 += e; else l1 += e;
            }
        }

        const float* kpst = kps + st*64;
        #pragma unroll
        for (int kc = 0; kc < 4; kc++) {
            unsigned ph[4], gh[4];
            ph[0] = pack2(s[2*kc][0],   s[2*kc][1]);
            ph[1] = pack2(s[2*kc][2],   s[2*kc][3]);
            ph[2] = pack2(s[2*kc+1][0], s[2*kc+1][1]);
            ph[3] = pack2(s[2*kc+1][2], s[2*kc+1][3]);
            {
                int c0 = kc*16 + 2*tig;
                float k0v = kpst[c0],     k1v = kpst[c0 + 1];
                float k8v = kpst[c0 + 8], k9v = kpst[c0 + 9];
                float ge00 = (c0     - r0loc <= relq) ? __expf(qp0 * k0v) : 0.f;
                float ge01 = (c0 + 1 - r0loc <= relq) ? __expf(qp0 * k1v) : 0.f;
                float ge10 = (c0     - r1loc <= relq) ? __expf(qp1 * k0v) : 0.f;
                float ge11 = (c0 + 1 - r1loc <= relq) ? __expf(qp1 * k1v) : 0.f;
                float ge08 = (c0 + 8 - r0loc <= relq) ? __expf(qp0 * k8v) : 0.f;
                float ge09 = (c0 + 9 - r0loc <= relq) ? __expf(qp0 * k9v) : 0.f;
                float ge18 = (c0 + 8 - r1loc <= relq) ? __expf(qp1 * k8v) : 0.f;
                float ge19 = (c0 + 9 - r1loc <= relq) ? __expf(qp1 * k9v) : 0.f;
                lg0 += ge00 + ge01 + ge08 + ge09;
                lg1 += ge10 + ge11 + ge18 + ge19;
                gh[0] = pack2(ge00, ge01);
                gh[1] = pack2(ge10, ge11);
                gh[2] = pack2(ge08, ge09);
                gh[3] = pack2(ge18, ge19);
            }
            // PV: O 2-term (ph x vh + ph x vl), Og 1-term (gh x vh)
            #pragma unroll
            for (int ndg = 0; ndg < 8; ndg++) {
                unsigned voff = (unsigned)(((st*256 + ndg*16 + lra)*VSTR + kc*16 + lca) * 2);
                unsigned vh4[4], vl4[4];
                ldsm_x4(vh4, uV + voff);
                ldsm_x4(vl4, uV + voff + (unsigned)(128*VSTR*2));
                int nd0 = ndg*2, nd1 = ndg*2 + 1;
                mma_f16(O[nd0],  ph, vh4[0], vh4[2]);
                mma_f16(O[nd1],  ph, vh4[1], vh4[3]);
                mma_f16(Og[nd0], gh, vh4[0], vh4[2]);
                mma_f16(Og[nd1], gh, vh4[1], vh4[3]);
                mma_f16(O[nd0],  ph, vl4[0], vl4[2]);
                mma_f16(O[nd1],  ph, vl4[1], vl4[3]);
            }
        }
        __syncthreads();
    }

    #pragma unroll
    for (int o = 1; o <= 2; o <<= 1) {
        l0  += __shfl_xor_sync(0xffffffffu, l0,  o);
        l1  += __shfl_xor_sync(0xffffffffu, l1,  o);
        lg0 += __shfl_xor_sync(0xffffffffu, lg0, o);
        lg1 += __shfl_xor_sync(0xffffffffu, lg1, o);
    }
    float c1a = (1.f - hs) / l0, c2a = hs / lg0;
    float c1b = (1.f - hs) / l1, c2b = hs / lg1;

    // epilogue: fp16 plane for Wo GEMM (Wo uses 2-term, A-lo not needed)
    size_t orow0 = (size_t)(b*TT + q0 + r0loc) * CC + h*DD;
    size_t orow1 = (size_t)(b*TT + q0 + r1loc) * CC + h*DD;
    #pragma unroll
    for (int nd = 0; nd < 16; nd++) {
        int d0 = nd*8 + 2*tig;
        float v0 = c1a*O[nd][0] + c2a*Og[nd][0];
        float v1 = c1a*O[nd][1] + c2a*Og[nd][1];
        *(unsigned*)&aoh[orow0 + d0] = pack2(v0, v1);
        v0 = c1b*O[nd][2] + c2b*Og[nd][2];
        v1 = c1b*O[nd][3] + c2b*Og[nd][3];
        *(unsigned*)&aoh[orow1 + d0] = pack2(v0, v1);
    }
}

// ---------------------------------------------------------------------------
// Launcher
// ---------------------------------------------------------------------------
extern "C" void kernel_launch(void* const* d_in, const int* in_sizes, int n_in,
                              void* d_out, int out_size)
{
    const float* x   = (const float*)d_in[0];
    const float* Wq  = (const float*)d_in[1];
    const float* Wk  = (const float*)d_in[2];
    const float* Wv  = (const float*)d_in[3];
    const float* Wo  = (const float*)d_in[4];
    const float* lng = (const float*)d_in[5];
    const float* lnb = (const float*)d_in[6];
    const float* hsc = (const float*)d_in[7];
    const float* hdr = (const float*)d_in[8];
    float* out = (float*)d_out;

    unsigned char* base = nullptr;
    cudaGetSymbolAddress((void**)&base, g_scratch);
    __half* xnh = (__half*)(base + OFF_XNH);
    __half* xnl = (__half*)(base + OFF_XNL);
    __half* wh  = (__half*)(base + OFF_WH);
    __half* wl  = (__half*)(base + OFF_WL);
    float* qf = (float*)(base + OFF_QF);
    float* kf = (float*)(base + OFF_KF);
    __half* qhp = (__half*)(base + OFF_QH);
    __half* khp = (__half*)(base + OFF_KH);
    __half* klp = (__half*)(base + OFF_KL);
    __half* vth = (__half*)(base + OFF_VTH);
    __half* vtl = (__half*)(base + OFF_VTL);
    __half* aoh = (__half*)(base + OFF_AOH);
    float* gqp = (float*)(base + OFF_QP);
    float* gkp = (float*)(base + OFF_KP);
    float2* cst = (float2*)(base + OFF_CS);

    cudaFuncSetAttribute(gemm2<0>,
                         cudaFuncAttributeMaxDynamicSharedMemorySize, GEMM_SMEM);
    cudaFuncSetAttribute(gemm2<1>,
                         cudaFuncAttributeMaxDynamicSharedMemorySize, GEMM_SMEM);
    cudaFuncSetAttribute(attn_mma,
                         cudaFuncAttributeMaxDynamicSharedMemorySize, ATTN_SMEM);

    rope_tab<<<TT, 64>>>(cst);
    ln_split<<<NTOK, 256>>>(x, lng, lnb, xnh, xnl);
    wsplit<<<4096, 256>>>(Wq, Wk, Wv, Wo, wh, wl);

    gemm2<0><<<dim3(24, NTOK/128), 256, GEMM_SMEM>>>(
        xnh, xnl, wh, wl, nullptr, qf, kf, vth, vtl);

    rope_kernel<<<BH*TT, 128>>>(qf, kf, hdr, cst, qhp, khp, klp, gqp, gkp);

    attn_mma<<<dim3(TT/128, BH), 256, ATTN_SMEM>>>(qhp, khp, klp, vth, vtl,
                                                   gqp, gkp, hsc, aoh);

    gemm2<1><<<dim3(8, NTOK/128), 256, GEMM_SMEM>>>(
        aoh, aoh, wh + 3*WPL, wl + 3*WPL, x, out, nullptr, nullptr, nullptr);
}

// round 16
// speedup vs baseline: 1.4413x; 1.1131x over previous
#include <cuda_runtime.h>
#include <cuda_fp16.h>
#include <math.h>

// Problem constants
#define BB 4
#define TT 2048
#define CC 1024
#define HH 8
#define DD 128
#define NTOK (BB*TT)          // 8192
#define BH   (BB*HH)          // 32
#define WPL  ((size_t)CC*CC)  // weight plane elems

// ---------------------------------------------------------------------------
// Scratch
// ---------------------------------------------------------------------------
#define SZ_F32 ((size_t)NTOK*CC*4)
#define SZ_BF  ((size_t)NTOK*CC*2)
#define SZ_WPL ((size_t)4*CC*CC*2)
#define SZ_P   ((size_t)BH*TT*4)
#define SZ_CS  ((size_t)TT*64*8)

#define OFF_XNH ((size_t)0)
#define OFF_WH  (OFF_XNH + SZ_BF)
#define OFF_WL  (OFF_WH + SZ_WPL)
#define OFF_QF  (OFF_WL + SZ_WPL)
#define OFF_KF  (OFF_QF + SZ_F32)
#define OFF_QH  (OFF_KF + SZ_F32)
#define OFF_KH  (OFF_QH + SZ_BF)
#define OFF_KL  (OFF_KH + SZ_BF)
#define OFF_VTH (OFF_KL + SZ_BF)
#define OFF_VTL (OFF_VTH + SZ_BF)
#define OFF_AOH (OFF_VTL + SZ_BF)
#define OFF_QP  (OFF_AOH + SZ_BF)
#define OFF_KP  (OFF_QP + SZ_P)
#define OFF_CS  (OFF_KP + SZ_P)
#define SCRATCH_BYTES (OFF_CS + SZ_CS)

__device__ __align__(256) unsigned char g_scratch[SCRATCH_BYTES];

// ---------------------------------------------------------------------------
// helpers (fp16 MMA path)
// ---------------------------------------------------------------------------
__device__ __forceinline__ void mma_f16(float* c, const unsigned* a,
                                        unsigned b0, unsigned b1) {
    asm volatile(
        "mma.sync.aligned.m16n8k16.row.col.f32.f16.f16.f32 "
        "{%0,%1,%2,%3},{%4,%5,%6,%7},{%8,%9},{%0,%1,%2,%3};"
        : "+f"(c[0]), "+f"(c[1]), "+f"(c[2]), "+f"(c[3])
        : "r"(a[0]), "r"(a[1]), "r"(a[2]), "r"(a[3]), "r"(b0), "r"(b1));
}

__device__ __forceinline__ void ldsm_x4(unsigned r[4], unsigned addr) {
    asm volatile("ldmatrix.sync.aligned.m8n8.x4.shared.b16 {%0,%1,%2,%3}, [%4];"
        : "=r"(r[0]), "=r"(r[1]), "=r"(r[2]), "=r"(r[3]) : "r"(addr));
}

#define CP16(dst, src) \
    asm volatile("cp.async.cg.shared.global [%0], [%1], 16;" :: "r"(dst), "l"(src))
#define CP4(dst, src) \
    asm volatile("cp.async.ca.shared.global [%0], [%1], 4;" :: "r"(dst), "l"(src))
#define CP_COMMIT() asm volatile("cp.async.commit_group;")
#define CP_WAIT0()  asm volatile("cp.async.wait_group 0;")
#define CP_WAIT1()  asm volatile("cp.async.wait_group 1;")

// fp16 hi/lo split of two floats
__device__ __forceinline__ void split2(float a, float b, unsigned& hi, unsigned& lo) {
    __half2 h = __floats2half2_rn(a, b);
    float la = a - __half2float(__low2half(h));
    float lb = b - __half2float(__high2half(h));
    __half2 l = __floats2half2_rn(la, lb);
    hi = *(unsigned*)&h;
    lo = *(unsigned*)&l;
}

// plain fp16 pack of two floats
__device__ __forceinline__ unsigned pack2(float a, float b) {
    __half2 h = __floats2half2_rn(a, b);
    return *(unsigned*)&h;
}

// ---------------------------------------------------------------------------
// LayerNorm -> fp16 hi plane (lo plane no longer needed: all GEMMs 2-term)
// ---------------------------------------------------------------------------
__global__ __launch_bounds__(256) void ln_split(
    const float* __restrict__ x, const float* __restrict__ gam,
    const float* __restrict__ bet,
    __half* __restrict__ xnh)
{
    int row = blockIdx.x;
    int t   = threadIdx.x;
    const float4* xr = (const float4*)(x + (size_t)row * CC);
    float4 v = xr[t];
    float s  = v.x + v.y + v.z + v.w;
    float ss = v.x*v.x + v.y*v.y + v.z*v.z + v.w*v.w;
    #pragma unroll
    for (int o = 16; o; o >>= 1) {
        s  += __shfl_xor_sync(0xffffffffu, s,  o);
        ss += __shfl_xor_sync(0xffffffffu, ss, o);
    }
    __shared__ float ws[8], wss[8];
    int wid = t >> 5;
    if ((t & 31) == 0) { ws[wid] = s; wss[wid] = ss; }
    __syncthreads();
    s = 0.f; ss = 0.f;
    #pragma unroll
    for (int i = 0; i < 8; i++) { s += ws[i]; ss += wss[i]; }
    float mu  = s * (1.f / CC);
    float var = ss * (1.f / CC) - mu * mu;
    float inv = rsqrtf(var + 1e-5f);
    float4 g4 = ((const float4*)gam)[t];
    float4 b4 = ((const float4*)bet)[t];
    float4 o;
    o.x = (v.x - mu) * inv * g4.x + b4.x;
    o.y = (v.y - mu) * inv * g4.y + b4.y;
    o.z = (v.z - mu) * inv * g4.z + b4.z;
    o.w = (v.w - mu) * inv * g4.w + b4.w;
    size_t off = (size_t)row * CC + t*4;
    *(uint2*)&xnh[off] = make_uint2(pack2(o.x, o.y), pack2(o.z, o.w));
}

// ---------------------------------------------------------------------------
// Split 4 weight matrices into fp16 hi/lo planes: plane order Wq,Wk,Wv,Wo
// ---------------------------------------------------------------------------
__global__ __launch_bounds__(256) void wsplit(
    const float* __restrict__ w0, const float* __restrict__ w1,
    const float* __restrict__ w2, const float* __restrict__ w3,
    __half* __restrict__ wh, __half* __restrict__ wl)
{
    int mid = blockIdx.x >> 10;
    const float* src = (mid == 0) ? w0 : (mid == 1) ? w1 : (mid == 2) ? w2 : w3;
    size_t idx = ((size_t)(blockIdx.x & 1023))*1024 + threadIdx.x*4;
    float4 v = *(const float4*)(src + idx);
    unsigned h0, l0, h1, l1;
    split2(v.x, v.y, h0, l0);
    split2(v.z, v.w, h1, l1);
    size_t off = (size_t)mid*WPL + idx;
    *(uint2*)&wh[off] = make_uint2(h0, h1);
    *(uint2*)&wl[off] = make_uint2(l0, l1);
}

// ---------------------------------------------------------------------------
// rope cos/sin table: cs[t*64+i] = (cos(t*inv_i), sin(t*inv_i))
// ---------------------------------------------------------------------------
__global__ __launch_bounds__(64) void rope_tab(float2* __restrict__ cs)
{
    int t = blockIdx.x, i = threadIdx.x;
    float inv = expf(-9.210340371976184f * (float)i * (1.f / 64.f));
    float sn, co;
    sincosf((float)t * inv, &sn, &co);
    cs[t*64 + i] = make_float2(co, sn);
}

// ---------------------------------------------------------------------------
// fp16 GEMM, uniform 2-term: acc = ah*(bh + bl). cp.async + ldmatrix,
// 128x128x32, 2 CTA/SM.
// MODE 0: QKV fused (grid.x=24; sel = x>>3): sel 0/1 -> fp32 head-major
//         q/k buffers; sel 2 -> transposed fp16 hi/lo planes [B,H,D,T]
// MODE 1: Wo, out0 = X + acc (fp32 row-major)
// ---------------------------------------------------------------------------
#define GSTR 40
#define GEMM_SMEM (3*2*128*GSTR*2)   // 61440 B (A hi, B hi, B lo)

template<int MODE>
__global__ __launch_bounds__(256, 2) void gemm2(
    const __half* __restrict__ Ah,
    const __half* __restrict__ Wh, const __half* __restrict__ Wl,
    const float* __restrict__ X,
    float* __restrict__ out0, float* __restrict__ out1,
    __half* __restrict__ oh, __half* __restrict__ ol)
{
    extern __shared__ __half smb[];
    __half* sAh = smb;
    __half* sBh = sAh + 2*128*GSTR;
    __half* sBl = sBh + 2*128*GSTR;
    unsigned uAh = (unsigned)__cvta_generic_to_shared(sAh);
    unsigned uBh = (unsigned)__cvta_generic_to_shared(sBh);
    unsigned uBl = (unsigned)__cvta_generic_to_shared(sBl);

    int tid = threadIdx.x, lane = tid & 31, warp = tid >> 5;
    int g = lane >> 2, tig = lane & 3;
    int wm = warp >> 1, wn = warp & 1;
    int sel = (MODE == 0) ? (blockIdx.x >> 3) : 0;
    int n0 = (MODE == 0) ? ((blockIdx.x & 7) << 7) : (blockIdx.x << 7);
    int m0 = blockIdx.y << 7;
    const __half* Wph = Wh + (size_t)sel*WPL;
    const __half* Wpl = Wl + (size_t)sel*WPL;

    int lr = tid >> 2;
    int lc8 = (tid & 3) * 8;

    float acc[16][4];
    #pragma unroll
    for (int i = 0; i < 16; i++)
        #pragma unroll
        for (int j = 0; j < 4; j++) acc[i][j] = 0.f;

    auto load_stage = [&](int buf, int k0) {
        size_t a0 = (size_t)(m0 + lr) * CC + k0 + lc8;
        size_t b0 = (size_t)(n0 + lr) * CC + k0 + lc8;
        unsigned d0 = (unsigned)(((buf*128 + lr)*GSTR + lc8) * 2);
        unsigned d1 = (unsigned)(((buf*128 + lr + 64)*GSTR + lc8) * 2);
        CP16(uAh + d0, Ah + a0);  CP16(uAh + d1, Ah + a0 + (size_t)64*CC);
        CP16(uBh + d0, Wph + b0); CP16(uBh + d1, Wph + b0 + (size_t)64*CC);
        CP16(uBl + d0, Wpl + b0); CP16(uBl + d1, Wpl + b0 + (size_t)64*CC);
    };

    load_stage(0, 0);
    CP_COMMIT();
    CP_WAIT0();
    __syncthreads();

    int lra = ((lane >> 3) & 1) * 8 + (lane & 7);
    int lca = (lane >> 4) * 8;
    const int NIT = CC / 32;

    for (int it = 0; it < NIT; it++) {
        int buf = it & 1;
        if (it + 1 < NIT) { load_stage(buf ^ 1, (it + 1) * 32); CP_COMMIT(); }

        int sb = buf * 128;
        #pragma unroll
        for (int kk = 0; kk < 2; kk++) {
            int col = kk*16 + lca;
            unsigned ah[2][4];
            #pragma unroll
            for (int mi = 0; mi < 2; mi++) {
                unsigned offA = (unsigned)(((sb + wm*32 + mi*16 + lra)*GSTR + col) * 2);
                ldsm_x4(ah[mi], uAh + offA);
            }
            #pragma unroll
            for (int np = 0; np < 2; np++) {
                unsigned b4h[2][4], b4l[2][4];
                #pragma unroll
                for (int u = 0; u < 2; u++) {
                    int ng = np*2 + u;
                    unsigned offB = (unsigned)(((sb + wn*64 + ng*16 + lra)*GSTR + col) * 2);
                    ldsm_x4(b4h[u], uBh + offB);
                    ldsm_x4(b4l[u], uBl + offB);
                }
                // term 1: ah x bh
                #pragma unroll
                for (int u = 0; u < 2; u++)
                    #pragma unroll
                    for (int hf = 0; hf < 2; hf++)
                        #pragma unroll
                        for (int mi = 0; mi < 2; mi++)
                            mma_f16(acc[mi*8 + (np*2+u)*2 + hf], ah[mi],
                                    b4h[u][hf], b4h[u][2 + hf]);
                // term 2: ah x bl
                #pragma unroll
                for (int u = 0; u < 2; u++)
                    #pragma unroll
                    for (int hf = 0; hf < 2; hf++)
                        #pragma unroll
                        for (int mi = 0; mi < 2; mi++)
                            mma_f16(acc[mi*8 + (np*2+u)*2 + hf], ah[mi],
                                    b4l[u][hf], b4l[u][2 + hf]);
            }
        }
        if (it + 1 < NIT) CP_WAIT0();
        __syncthreads();
    }

    // epilogue
    #pragma unroll
    for (int mi = 0; mi < 2; mi++) {
        #pragma unroll
        for (int ni = 0; ni < 8; ni++) {
            const float* c = acc[mi*8 + ni];
            int r0 = m0 + wm*32 + mi*16 + g;
            int c0 = n0 + wn*64 + ni*8 + 2*tig;
            #pragma unroll
            for (int half = 0; half < 2; half++) {
                int r = r0 + half*8;
                float v0 = c[half*2], v1 = c[half*2 + 1];
                if (MODE == 1) {
                    size_t o = (size_t)r * CC + c0;
                    float2 xv = *(const float2*)&X[o];
                    *(float2*)&out0[o] = make_float2(xv.x + v0, xv.y + v1);
                } else if (sel < 2) {
                    int b = r >> 11, t = r & 2047, h = c0 >> 7, d = c0 & 127;
                    float* outp = sel ? out1 : out0;
                    *(float2*)&outp[(((size_t)(b*HH + h) * TT) + t) * DD + d] =
                        make_float2(v0, v1);
                } else {
                    int b = r >> 11, t = r & 2047, h = c0 >> 7, d = c0 & 127;
                    size_t rb = ((size_t)((b*HH + h)*DD + d)) * TT + t;
                    __half h0 = __float2half_rn(v0);
                    __half h1 = __float2half_rn(v1);
                    oh[rb]      = h0;
                    ol[rb]      = __float2half_rn(v0 - __half2float(h0));
                    oh[rb + TT] = h1;
                    ol[rb + TT] = __float2half_rn(v1 - __half2float(h1));
                }
            }
        }
    }
}

// ---------------------------------------------------------------------------
// RoPE on q,k: read fp32 head-major, write fp16 planes + qp/kp.
// Q gets hi plane only (S-GEMM is 2-term); K gets hi+lo planes.
// ---------------------------------------------------------------------------
__global__ __launch_bounds__(128) void rope_kernel(
    const float* __restrict__ qf, const float* __restrict__ kf,
    const float* __restrict__ dirs, const float2* __restrict__ cs,
    __half* __restrict__ qh,
    __half* __restrict__ kh, __half* __restrict__ kl,
    float* __restrict__ qp, float* __restrict__ kp)
{
    int idx = blockIdx.x;
    int t = idx & (TT - 1);
    int h = (idx >> 11) & (HH - 1);
    int tid = threadIdx.x;
    int i = tid & 63;
    bool isq = tid < 64;
    const float* src = (isq ? qf : kf) + (size_t)idx * DD;
    float x1 = src[i], x2 = src[i + 64];
    float2 cssn = cs[t*64 + i];
    float y1 = x1 * cssn.x - x2 * cssn.y;
    float y2 = x2 * cssn.x + x1 * cssn.y;
    size_t o = (size_t)idx * DD;
    __half h1 = __float2half_rn(y1);
    __half h2 = __float2half_rn(y2);
    if (isq) {
        qh[o + i]      = h1;
        qh[o + i + 64] = h2;
    } else {
        kh[o + i]      = h1;
        kl[o + i]      = __float2half_rn(y1 - __half2float(h1));
        kh[o + i + 64] = h2;
        kl[o + i + 64] = __float2half_rn(y2 - __half2float(h2));
    }
    __shared__ float red[6];
    if (i < 3) red[(tid >> 6) * 3 + i] = y1 * dirs[h * 3 + i];
    __syncthreads();
    if (tid == 0)  qp[idx] = red[0] + red[1] + red[2];
    if (tid == 64) kp[idx] = red[3] + red[4] + red[5];
}

// ---------------------------------------------------------------------------
// ONE-PASS dual-softmax flash attention, fp16 MMA.
// S: 2-term (qh x (kh + kl)). O PV: 2-term (ph x (vh + vl)). Og PV: 1-term.
// Br=128 (256 thr, 8 warps, warp owns 16 rows), Bc=64.
// ---------------------------------------------------------------------------
#define KSTR 136
#define VSTR 72
#define Q_ELE (128*KSTR)
#define K_ELE (2*2*64*KSTR)
#define V_ELE (2*2*128*VSTR)
#define ATTN_SMEM ((Q_ELE + K_ELE + V_ELE)*2 + 2*64*4)
#define SCALE 0.08838834764831845f

__global__ __launch_bounds__(256, 1) void attn_mma(
    const __half* __restrict__ qh,
    const __half* __restrict__ kh, const __half* __restrict__ kl,
    const __half* __restrict__ vth, const __half* __restrict__ vtl,
    const float* __restrict__ qp, const float* __restrict__ kp,
    const float* __restrict__ hsc,
    __half* __restrict__ aoh)
{
    extern __shared__ unsigned char sma[];
    __half* Qh = (__half*)sma;
    __half* Kb = Qh + Q_ELE;
    __half* Vb = Kb + K_ELE;
    float* kps = (float*)(Vb + V_ELE);

    unsigned uQ = (unsigned)__cvta_generic_to_shared(Qh);
    unsigned uK = (unsigned)__cvta_generic_to_shared(Kb);
    unsigned uV = (unsigned)__cvta_generic_to_shared(Vb);
    unsigned uKps = (unsigned)__cvta_generic_to_shared(kps);

    int bh = blockIdx.y;
    int b = bh >> 3, h = bh & 7;
    int q0 = (gridDim.x - 1 - blockIdx.x) << 7;
    size_t tb = (size_t)bh * TT;
    int tid = threadIdx.x;
    int lane = tid & 31, warp = tid >> 5;
    int g = lane >> 2, tig = lane & 3;
    int r0loc = warp*16 + g, r1loc = r0loc + 8;
    int lra = ((lane >> 3) & 1) * 8 + (lane & 7);
    int lca = (lane >> 4) * 8;

    {
        const __half* qhg = qh + (tb + q0) * DD;
        for (int i = tid; i < 2048; i += 256) {
            int r = i >> 4, c = (i & 15) << 3;
            *(uint4*)&Qh[r*KSTR + c] = *(const uint4*)&qhg[r*DD + c];
        }
    }
    float hs  = hsc[h];
    float qp0 = qp[tb + q0 + r0loc];
    float qp1 = qp[tb + q0 + r1loc];
    int ntiles = (q0 >> 6) + 2;

    auto prefetch = [&](int st, int n0) {
        const __half* khg = kh + (tb + n0) * DD;
        const __half* klg = kl + (tb + n0) * DD;
        for (int i = tid; i < 1024; i += 256) {
            int r = i >> 4, c = (i & 15) << 3;
            CP16(uK + (unsigned)(((st*128 + r)*KSTR + c) * 2),      khg + r*DD + c);
            CP16(uK + (unsigned)(((st*128 + 64 + r)*KSTR + c) * 2), klg + r*DD + c);
        }
        const __half* vhg = vth + (size_t)bh*DD*TT + n0;
        const __half* vlg = vtl + (size_t)bh*DD*TT + n0;
        for (int i = tid; i < 1024; i += 256) {
            int d = i >> 3, c = (i & 7) << 3;
            CP16(uV + (unsigned)(((st*256 + d)*VSTR + c) * 2),       vhg + (size_t)d*TT + c);
            CP16(uV + (unsigned)(((st*256 + 128 + d)*VSTR + c) * 2), vlg + (size_t)d*TT + c);
        }
        if (tid < 64) CP4(uKps + (unsigned)((st*64 + tid) * 4), kp + tb + n0 + tid);
    };

    float O[16][4], Og[16][4];
    #pragma unroll
    for (int i = 0; i < 16; i++)
        #pragma unroll
        for (int j = 0; j < 4; j++) { O[i][j] = 0.f; Og[i][j] = 0.f; }
    float l0 = 0.f, l1 = 0.f, lg0 = 0.f, lg1 = 0.f;

    prefetch(0, 0);
    CP_COMMIT();
    for (int it = 0; it < ntiles; it++) {
        int st = it & 1;
        int n0 = it << 6;
        if (it + 1 < ntiles) { prefetch(st ^ 1, (it + 1) << 6); CP_COMMIT(); CP_WAIT1(); }
        else                 { CP_WAIT0(); }
        __syncthreads();

        // ---- S = Q K^T (2-term fp16: qh x kh + qh x kl)
        float s[8][4];
        #pragma unroll
        for (int i = 0; i < 8; i++)
            #pragma unroll
            for (int j = 0; j < 4; j++) s[i][j] = 0.f;
        #pragma unroll
        for (int kk = 0; kk < 8; kk++) {
            int col = kk*16 + lca;
            unsigned qoff = (unsigned)(((warp*16 + lra)*KSTR + col) * 2);
            unsigned qa[4];
            ldsm_x4(qa, uQ + qoff);
            #pragma unroll
            for (int np = 0; np < 2; np++) {
                unsigned kh4[2][4], kl4[2][4];
                #pragma unroll
                for (int u = 0; u < 2; u++) {
                    int ng = np*2 + u;
                    unsigned koff = (unsigned)(((st*128 + ng*16 + lra)*KSTR + col) * 2);
                    ldsm_x4(kh4[u], uK + koff);
                    ldsm_x4(kl4[u], uK + koff + (unsigned)(64*KSTR*2));
                }
                #pragma unroll
                for (int u = 0; u < 2; u++)
                    #pragma unroll
                    for (int hf = 0; hf < 2; hf++)
                        mma_f16(s[(np*2+u)*2 + hf], qa, kh4[u][hf], kh4[u][2 + hf]);
                #pragma unroll
                for (int u = 0; u < 2; u++)
                    #pragma unroll
                    for (int hf = 0; hf < 2; hf++)
                        mma_f16(s[(np*2+u)*2 + hf], qa, kl4[u][hf], kl4[u][2 + hf]);
            }
        }

        int relq = q0 - n0;
        #pragma unroll
        for (int ni = 0; ni < 8; ni++) {
            #pragma unroll
            for (int j = 0; j < 4; j++) {
                int cl = ni*8 + 2*tig + (j & 1);
                int rl = (j < 2) ? r0loc : r1loc;
                bool ok = (cl - rl <= relq);
                float e = ok ? __expf(s[ni][j] * SCALE) : 0.f;
                s[ni][j] = e;
                if (j < 2) l0 += e; else l1 += e;
            }
        }

        const float* kpst = kps + st*64;
        #pragma unroll
        for (int kc = 0; kc < 4; kc++) {
            unsigned ph[4], gh[4];
            ph[0] = pack2(s[2*kc][0],   s[2*kc][1]);
            ph[1] = pack2(s[2*kc][2],   s[2*kc][3]);
            ph[2] = pack2(s[2*kc+1][0], s[2*kc+1][1]);
            ph[3] = pack2(s[2*kc+1][2], s[2*kc+1][3]);
            {
                int c0 = kc*16 + 2*tig;
                float k0v = kpst[c0],     k1v = kpst[c0 + 1];
                float k8v = kpst[c0 + 8], k9v = kpst[c0 + 9];
                float ge00 = (c0     - r0loc <= relq) ? __expf(qp0 * k0v) : 0.f;
                float ge01 = (c0 + 1 - r0loc <= relq) ? __expf(qp0 * k1v) : 0.f;
                float ge10 = (c0     - r1loc <= relq) ? __expf(qp1 * k0v) : 0.f;
                float ge11 = (c0 + 1 - r1loc <= relq) ? __expf(qp1 * k1v) : 0.f;
                float ge08 = (c0 + 8 - r0loc <= relq) ? __expf(qp0 * k8v) : 0.f;
                float ge09 = (c0 + 9 - r0loc <= relq) ? __expf(qp0 * k9v) : 0.f;
                float ge18 = (c0 + 8 - r1loc <= relq) ? __expf(qp1 * k8v) : 0.f;
                float ge19 = (c0 + 9 - r1loc <= relq) ? __expf(qp1 * k9v) : 0.f;
                lg0 += ge00 + ge01 + ge08 + ge09;
                lg1 += ge10 + ge11 + ge18 + ge19;
                gh[0] = pack2(ge00, ge01);
                gh[1] = pack2(ge10, ge11);
                gh[2] = pack2(ge08, ge09);
                gh[3] = pack2(ge18, ge19);
            }
            // PV: O 2-term (ph x vh + ph x vl), Og 1-term (gh x vh)
            #pragma unroll
            for (int ndg = 0; ndg < 8; ndg++) {
                unsigned voff = (unsigned)(((st*256 + ndg*16 + lra)*VSTR + kc*16 + lca) * 2);
                unsigned vh4[4], vl4[4];
                ldsm_x4(vh4, uV + voff);
                ldsm_x4(vl4, uV + voff + (unsigned)(128*VSTR*2));
                int nd0 = ndg*2, nd1 = ndg*2 + 1;
                mma_f16(O[nd0],  ph, vh4[0], vh4[2]);
                mma_f16(O[nd1],  ph, vh4[1], vh4[3]);
                mma_f16(Og[nd0], gh, vh4[0], vh4[2]);
                mma_f16(Og[nd1], gh, vh4[1], vh4[3]);
                mma_f16(O[nd0],  ph, vl4[0], vl4[2]);
                mma_f16(O[nd1],  ph, vl4[1], vl4[3]);
            }
        }
        __syncthreads();
    }

    #pragma unroll
    for (int o = 1; o <= 2; o <<= 1) {
        l0  += __shfl_xor_sync(0xffffffffu, l0,  o);
        l1  += __shfl_xor_sync(0xffffffffu, l1,  o);
        lg0 += __shfl_xor_sync(0xffffffffu, lg0, o);
        lg1 += __shfl_xor_sync(0xffffffffu, lg1, o);
    }
    float c1a = (1.f - hs) / l0, c2a = hs / lg0;
    float c1b = (1.f - hs) / l1, c2b = hs / lg1;

    // epilogue: fp16 plane for Wo GEMM
    size_t orow0 = (size_t)(b*TT + q0 + r0loc) * CC + h*DD;
    size_t orow1 = (size_t)(b*TT + q0 + r1loc) * CC + h*DD;
    #pragma unroll
    for (int nd = 0; nd < 16; nd++) {
        int d0 = nd*8 + 2*tig;
        float v0 = c1a*O[nd][0] + c2a*Og[nd][0];
        float v1 = c1a*O[nd][1] + c2a*Og[nd][1];
        *(unsigned*)&aoh[orow0 + d0] = pack2(v0, v1);
        v0 = c1b*O[nd][2] + c2b*Og[nd][2];
        v1 = c1b*O[nd][3] + c2b*Og[nd][3];
        *(unsigned*)&aoh[orow1 + d0] = pack2(v0, v1);
    }
}

// ---------------------------------------------------------------------------
// Launcher
// ---------------------------------------------------------------------------
extern "C" void kernel_launch(void* const* d_in, const int* in_sizes, int n_in,
                              void* d_out, int out_size)
{
    const float* x   = (const float*)d_in[0];
    const float* Wq  = (const float*)d_in[1];
    const float* Wk  = (const float*)d_in[2];
    const float* Wv  = (const float*)d_in[3];
    const float* Wo  = (const float*)d_in[4];
    const float* lng = (const float*)d_in[5];
    const float* lnb = (const float*)d_in[6];
    const float* hsc = (const float*)d_in[7];
    const float* hdr = (const float*)d_in[8];
    float* out = (float*)d_out;

    unsigned char* base = nullptr;
    cudaGetSymbolAddress((void**)&base, g_scratch);
    __half* xnh = (__half*)(base + OFF_XNH);
    __half* wh  = (__half*)(base + OFF_WH);
    __half* wl  = (__half*)(base + OFF_WL);
    float* qf = (float*)(base + OFF_QF);
    float* kf = (float*)(base + OFF_KF);
    __half* qhp = (__half*)(base + OFF_QH);
    __half* khp = (__half*)(base + OFF_KH);
    __half* klp = (__half*)(base + OFF_KL);
    __half* vth = (__half*)(base + OFF_VTH);
    __half* vtl = (__half*)(base + OFF_VTL);
    __half* aoh = (__half*)(base + OFF_AOH);
    float* gqp = (float*)(base + OFF_QP);
    float* gkp = (float*)(base + OFF_KP);
    float2* cst = (float2*)(base + OFF_CS);

    cudaFuncSetAttribute(gemm2<0>,
                         cudaFuncAttributeMaxDynamicSharedMemorySize, GEMM_SMEM);
    cudaFuncSetAttribute(gemm2<1>,
                         cudaFuncAttributeMaxDynamicSharedMemorySize, GEMM_SMEM);
    cudaFuncSetAttribute(attn_mma,
                         cudaFuncAttributeMaxDynamicSharedMemorySize, ATTN_SMEM);

    rope_tab<<<TT, 64>>>(cst);
    ln_split<<<NTOK, 256>>>(x, lng, lnb, xnh);
    wsplit<<<4096, 256>>>(Wq, Wk, Wv, Wo, wh, wl);

    gemm2<0><<<dim3(24, NTOK/128), 256, GEMM_SMEM>>>(
        xnh, wh, wl, nullptr, qf, kf, vth, vtl);

    rope_kernel<<<BH*TT, 128>>>(qf, kf, hdr, cst, qhp, khp, klp, gqp, gkp);

    attn_mma<<<dim3(TT/128, BH), 256, ATTN_SMEM>>>(qhp, khp, klp, vth, vtl,
                                                   gqp, gkp, hsc, aoh);

    gemm2<1><<<dim3(8, NTOK/128), 256, GEMM_SMEM>>>(
        aoh, wh + 3*WPL, wl + 3*WPL, x, out, nullptr, nullptr, nullptr);
}

// round 17
// speedup vs baseline: 1.5787x; 1.0953x over previous
#include <cuda_runtime.h>
#include <cuda_fp16.h>
#include <math.h>

// Problem constants
#define BB 4
#define TT 2048
#define CC 1024
#define HH 8
#define DD 128
#define NTOK (BB*TT)          // 8192
#define BH   (BB*HH)          // 32
#define WPL  ((size_t)CC*CC)  // weight plane elems

// ---------------------------------------------------------------------------
// Scratch
// ---------------------------------------------------------------------------
#define SZ_F32 ((size_t)NTOK*CC*4)
#define SZ_BF  ((size_t)NTOK*CC*2)
#define SZ_WPL ((size_t)4*CC*CC*2)
#define SZ_P   ((size_t)BH*TT*4)
#define SZ_CS  ((size_t)TT*64*8)

#define OFF_XNH ((size_t)0)
#define OFF_WH  (OFF_XNH + SZ_BF)
#define OFF_WL  (OFF_WH + SZ_WPL)
#define OFF_QF  (OFF_WL + SZ_WPL)
#define OFF_KF  (OFF_QF + SZ_F32)
#define OFF_QH  (OFF_KF + SZ_F32)
#define OFF_KH  (OFF_QH + SZ_BF)
#define OFF_KL  (OFF_KH + SZ_BF)
#define OFF_VTH (OFF_KL + SZ_BF)
#define OFF_AOH (OFF_VTH + SZ_BF)
#define OFF_QP  (OFF_AOH + SZ_BF)
#define OFF_KP  (OFF_QP + SZ_P)
#define OFF_CS  (OFF_KP + SZ_P)
#define SCRATCH_BYTES (OFF_CS + SZ_CS)

__device__ __align__(256) unsigned char g_scratch[SCRATCH_BYTES];

// ---------------------------------------------------------------------------
// helpers (fp16 MMA path)
// ---------------------------------------------------------------------------
__device__ __forceinline__ void mma_f16(float* c, const unsigned* a,
                                        unsigned b0, unsigned b1) {
    asm volatile(
        "mma.sync.aligned.m16n8k16.row.col.f32.f16.f16.f32 "
        "{%0,%1,%2,%3},{%4,%5,%6,%7},{%8,%9},{%0,%1,%2,%3};"
        : "+f"(c[0]), "+f"(c[1]), "+f"(c[2]), "+f"(c[3])
        : "r"(a[0]), "r"(a[1]), "r"(a[2]), "r"(a[3]), "r"(b0), "r"(b1));
}

__device__ __forceinline__ void ldsm_x4(unsigned r[4], unsigned addr) {
    asm volatile("ldmatrix.sync.aligned.m8n8.x4.shared.b16 {%0,%1,%2,%3}, [%4];"
        : "=r"(r[0]), "=r"(r[1]), "=r"(r[2]), "=r"(r[3]) : "r"(addr));
}

#define CP16(dst, src) \
    asm volatile("cp.async.cg.shared.global [%0], [%1], 16;" :: "r"(dst), "l"(src))
#define CP4(dst, src) \
    asm volatile("cp.async.ca.shared.global [%0], [%1], 4;" :: "r"(dst), "l"(src))
#define CP_COMMIT() asm volatile("cp.async.commit_group;")
#define CP_WAIT0()  asm volatile("cp.async.wait_group 0;")
#define CP_WAIT1()  asm volatile("cp.async.wait_group 1;")

// fp16 hi/lo split of two floats
__device__ __forceinline__ void split2(float a, float b, unsigned& hi, unsigned& lo) {
    __half2 h = __floats2half2_rn(a, b);
    float la = a - __half2float(__low2half(h));
    float lb = b - __half2float(__high2half(h));
    __half2 l = __floats2half2_rn(la, lb);
    hi = *(unsigned*)&h;
    lo = *(unsigned*)&l;
}

// plain fp16 pack of two floats
__device__ __forceinline__ unsigned pack2(float a, float b) {
    __half2 h = __floats2half2_rn(a, b);
    return *(unsigned*)&h;
}

// ---------------------------------------------------------------------------
// LayerNorm -> fp16 hi plane
// ---------------------------------------------------------------------------
__global__ __launch_bounds__(256) void ln_split(
    const float* __restrict__ x, const float* __restrict__ gam,
    const float* __restrict__ bet,
    __half* __restrict__ xnh)
{
    int row = blockIdx.x;
    int t   = threadIdx.x;
    const float4* xr = (const float4*)(x + (size_t)row * CC);
    float4 v = xr[t];
    float s  = v.x + v.y + v.z + v.w;
    float ss = v.x*v.x + v.y*v.y + v.z*v.z + v.w*v.w;
    #pragma unroll
    for (int o = 16; o; o >>= 1) {
        s  += __shfl_xor_sync(0xffffffffu, s,  o);
        ss += __shfl_xor_sync(0xffffffffu, ss, o);
    }
    __shared__ float ws[8], wss[8];
    int wid = t >> 5;
    if ((t & 31) == 0) { ws[wid] = s; wss[wid] = ss; }
    __syncthreads();
    s = 0.f; ss = 0.f;
    #pragma unroll
    for (int i = 0; i < 8; i++) { s += ws[i]; ss += wss[i]; }
    float mu  = s * (1.f / CC);
    float var = ss * (1.f / CC) - mu * mu;
    float inv = rsqrtf(var + 1e-5f);
    float4 g4 = ((const float4*)gam)[t];
    float4 b4 = ((const float4*)bet)[t];
    float4 o;
    o.x = (v.x - mu) * inv * g4.x + b4.x;
    o.y = (v.y - mu) * inv * g4.y + b4.y;
    o.z = (v.z - mu) * inv * g4.z + b4.z;
    o.w = (v.w - mu) * inv * g4.w + b4.w;
    size_t off = (size_t)row * CC + t*4;
    *(uint2*)&xnh[off] = make_uint2(pack2(o.x, o.y), pack2(o.z, o.w));
}

// ---------------------------------------------------------------------------
// Split 4 weight matrices into fp16 hi/lo planes: plane order Wq,Wk,Wv,Wo
// ---------------------------------------------------------------------------
__global__ __launch_bounds__(256) void wsplit(
    const float* __restrict__ w0, const float* __restrict__ w1,
    const float* __restrict__ w2, const float* __restrict__ w3,
    __half* __restrict__ wh, __half* __restrict__ wl)
{
    int mid = blockIdx.x >> 10;
    const float* src = (mid == 0) ? w0 : (mid == 1) ? w1 : (mid == 2) ? w2 : w3;
    size_t idx = ((size_t)(blockIdx.x & 1023))*1024 + threadIdx.x*4;
    float4 v = *(const float4*)(src + idx);
    unsigned h0, l0, h1, l1;
    split2(v.x, v.y, h0, l0);
    split2(v.z, v.w, h1, l1);
    size_t off = (size_t)mid*WPL + idx;
    *(uint2*)&wh[off] = make_uint2(h0, h1);
    *(uint2*)&wl[off] = make_uint2(l0, l1);
}

// ---------------------------------------------------------------------------
// rope cos/sin table: cs[t*64+i] = (cos(t*inv_i), sin(t*inv_i))
// ---------------------------------------------------------------------------
__global__ __launch_bounds__(64) void rope_tab(float2* __restrict__ cs)
{
    int t = blockIdx.x, i = threadIdx.x;
    float inv = expf(-9.210340371976184f * (float)i * (1.f / 64.f));
    float sn, co;
    sincosf((float)t * inv, &sn, &co);
    cs[t*64 + i] = make_float2(co, sn);
}

// ---------------------------------------------------------------------------
// fp16 GEMM, uniform 2-term: acc = ah*(bh + bl). cp.async + ldmatrix,
// 128x128x32, 2 CTA/SM.
// MODE 0: QKV fused (grid.x=24; sel = x>>3): sel 0/1 -> fp32 head-major
//         q/k buffers; sel 2 -> transposed fp16 hi plane [B,H,D,T]
// MODE 1: Wo, out0 = X + acc (fp32 row-major)
// ---------------------------------------------------------------------------
#define GSTR 40
#define GEMM_SMEM (3*2*128*GSTR*2)   // 61440 B (A hi, B hi, B lo)

template<int MODE>
__global__ __launch_bounds__(256, 2) void gemm2(
    const __half* __restrict__ Ah,
    const __half* __restrict__ Wh, const __half* __restrict__ Wl,
    const float* __restrict__ X,
    float* __restrict__ out0, float* __restrict__ out1,
    __half* __restrict__ oh)
{
    extern __shared__ __half smb[];
    __half* sAh = smb;
    __half* sBh = sAh + 2*128*GSTR;
    __half* sBl = sBh + 2*128*GSTR;
    unsigned uAh = (unsigned)__cvta_generic_to_shared(sAh);
    unsigned uBh = (unsigned)__cvta_generic_to_shared(sBh);
    unsigned uBl = (unsigned)__cvta_generic_to_shared(sBl);

    int tid = threadIdx.x, lane = tid & 31, warp = tid >> 5;
    int g = lane >> 2, tig = lane & 3;
    int wm = warp >> 1, wn = warp & 1;
    int sel = (MODE == 0) ? (blockIdx.x >> 3) : 0;
    int n0 = (MODE == 0) ? ((blockIdx.x & 7) << 7) : (blockIdx.x << 7);
    int m0 = blockIdx.y << 7;
    const __half* Wph = Wh + (size_t)sel*WPL;
    const __half* Wpl = Wl + (size_t)sel*WPL;

    int lr = tid >> 2;
    int lc8 = (tid & 3) * 8;

    float acc[16][4];
    #pragma unroll
    for (int i = 0; i < 16; i++)
        #pragma unroll
        for (int j = 0; j < 4; j++) acc[i][j] = 0.f;

    auto load_stage = [&](int buf, int k0) {
        size_t a0 = (size_t)(m0 + lr) * CC + k0 + lc8;
        size_t b0 = (size_t)(n0 + lr) * CC + k0 + lc8;
        unsigned d0 = (unsigned)(((buf*128 + lr)*GSTR + lc8) * 2);
        unsigned d1 = (unsigned)(((buf*128 + lr + 64)*GSTR + lc8) * 2);
        CP16(uAh + d0, Ah + a0);  CP16(uAh + d1, Ah + a0 + (size_t)64*CC);
        CP16(uBh + d0, Wph + b0); CP16(uBh + d1, Wph + b0 + (size_t)64*CC);
        CP16(uBl + d0, Wpl + b0); CP16(uBl + d1, Wpl + b0 + (size_t)64*CC);
    };

    load_stage(0, 0);
    CP_COMMIT();
    CP_WAIT0();
    __syncthreads();

    int lra = ((lane >> 3) & 1) * 8 + (lane & 7);
    int lca = (lane >> 4) * 8;
    const int NIT = CC / 32;

    for (int it = 0; it < NIT; it++) {
        int buf = it & 1;
        if (it + 1 < NIT) { load_stage(buf ^ 1, (it + 1) * 32); CP_COMMIT(); }

        int sb = buf * 128;
        #pragma unroll
        for (int kk = 0; kk < 2; kk++) {
            int col = kk*16 + lca;
            unsigned ah[2][4];
            #pragma unroll
            for (int mi = 0; mi < 2; mi++) {
                unsigned offA = (unsigned)(((sb + wm*32 + mi*16 + lra)*GSTR + col) * 2);
                ldsm_x4(ah[mi], uAh + offA);
            }
            #pragma unroll
            for (int np = 0; np < 2; np++) {
                unsigned b4h[2][4], b4l[2][4];
                #pragma unroll
                for (int u = 0; u < 2; u++) {
                    int ng = np*2 + u;
                    unsigned offB = (unsigned)(((sb + wn*64 + ng*16 + lra)*GSTR + col) * 2);
                    ldsm_x4(b4h[u], uBh + offB);
                    ldsm_x4(b4l[u], uBl + offB);
                }
                // term 1: ah x bh
                #pragma unroll
                for (int u = 0; u < 2; u++)
                    #pragma unroll
                    for (int hf = 0; hf < 2; hf++)
                        #pragma unroll
                        for (int mi = 0; mi < 2; mi++)
                            mma_f16(acc[mi*8 + (np*2+u)*2 + hf], ah[mi],
                                    b4h[u][hf], b4h[u][2 + hf]);
                // term 2: ah x bl
                #pragma unroll
                for (int u = 0; u < 2; u++)
                    #pragma unroll
                    for (int hf = 0; hf < 2; hf++)
                        #pragma unroll
                        for (int mi = 0; mi < 2; mi++)
                            mma_f16(acc[mi*8 + (np*2+u)*2 + hf], ah[mi],
                                    b4l[u][hf], b4l[u][2 + hf]);
            }
        }
        if (it + 1 < NIT) CP_WAIT0();
        __syncthreads();
    }

    // epilogue
    #pragma unroll
    for (int mi = 0; mi < 2; mi++) {
        #pragma unroll
        for (int ni = 0; ni < 8; ni++) {
            const float* c = acc[mi*8 + ni];
            int r0 = m0 + wm*32 + mi*16 + g;
            int c0 = n0 + wn*64 + ni*8 + 2*tig;
            #pragma unroll
            for (int half = 0; half < 2; half++) {
                int r = r0 + half*8;
                float v0 = c[half*2], v1 = c[half*2 + 1];
                if (MODE == 1) {
                    size_t o = (size_t)r * CC + c0;
                    float2 xv = *(const float2*)&X[o];
                    *(float2*)&out0[o] = make_float2(xv.x + v0, xv.y + v1);
                } else if (sel < 2) {
                    int b = r >> 11, t = r & 2047, h = c0 >> 7, d = c0 & 127;
                    float* outp = sel ? out1 : out0;
                    *(float2*)&outp[(((size_t)(b*HH + h) * TT) + t) * DD + d] =
                        make_float2(v0, v1);
                } else {
                    int b = r >> 11, t = r & 2047, h = c0 >> 7, d = c0 & 127;
                    size_t rb = ((size_t)((b*HH + h)*DD + d)) * TT + t;
                    oh[rb]      = __float2half_rn(v0);
                    oh[rb + TT] = __float2half_rn(v1);
                }
            }
        }
    }
}

// ---------------------------------------------------------------------------
// RoPE on q,k: read fp32 head-major, write fp16 planes + qp/kp.
// Q gets hi plane only; K gets hi+lo planes (score path stays 2-term).
// ---------------------------------------------------------------------------
__global__ __launch_bounds__(128) void rope_kernel(
    const float* __restrict__ qf, const float* __restrict__ kf,
    const float* __restrict__ dirs, const float2* __restrict__ cs,
    __half* __restrict__ qh,
    __half* __restrict__ kh, __half* __restrict__ kl,
    float* __restrict__ qp, float* __restrict__ kp)
{
    int idx = blockIdx.x;
    int t = idx & (TT - 1);
    int h = (idx >> 11) & (HH - 1);
    int tid = threadIdx.x;
    int i = tid & 63;
    bool isq = tid < 64;
    const float* src = (isq ? qf : kf) + (size_t)idx * DD;
    float x1 = src[i], x2 = src[i + 64];
    float2 cssn = cs[t*64 + i];
    float y1 = x1 * cssn.x - x2 * cssn.y;
    float y2 = x2 * cssn.x + x1 * cssn.y;
    size_t o = (size_t)idx * DD;
    __half h1 = __float2half_rn(y1);
    __half h2 = __float2half_rn(y2);
    if (isq) {
        qh[o + i]      = h1;
        qh[o + i + 64] = h2;
    } else {
        kh[o + i]      = h1;
        kl[o + i]      = __float2half_rn(y1 - __half2float(h1));
        kh[o + i + 64] = h2;
        kl[o + i + 64] = __float2half_rn(y2 - __half2float(h2));
    }
    __shared__ float red[6];
    if (i < 3) red[(tid >> 6) * 3 + i] = y1 * dirs[h * 3 + i];
    __syncthreads();
    if (tid == 0)  qp[idx] = red[0] + red[1] + red[2];
    if (tid == 64) kp[idx] = red[3] + red[4] + red[5];
}

// ---------------------------------------------------------------------------
// ONE-PASS dual-softmax flash attention, fp16 MMA.
// S: 2-term (qh x (kh + kl)). O PV: 1-term (ph x vh). Og PV: 1-term.
// Br=128 (256 thr, 8 warps, warp owns 16 rows), Bc=64.
// ---------------------------------------------------------------------------
#define KSTR 136
#define VSTR 72
#define Q_ELE (128*KSTR)
#define K_ELE (2*2*64*KSTR)
#define V_ELE (2*128*VSTR)
#define ATTN_SMEM ((Q_ELE + K_ELE + V_ELE)*2 + 2*64*4)
#define SCALE 0.08838834764831845f

__global__ __launch_bounds__(256, 1) void attn_mma(
    const __half* __restrict__ qh,
    const __half* __restrict__ kh, const __half* __restrict__ kl,
    const __half* __restrict__ vth,
    const float* __restrict__ qp, const float* __restrict__ kp,
    const float* __restrict__ hsc,
    __half* __restrict__ aoh)
{
    extern __shared__ unsigned char sma[];
    __half* Qh = (__half*)sma;
    __half* Kb = Qh + Q_ELE;
    __half* Vb = Kb + K_ELE;
    float* kps = (float*)(Vb + V_ELE);

    unsigned uQ = (unsigned)__cvta_generic_to_shared(Qh);
    unsigned uK = (unsigned)__cvta_generic_to_shared(Kb);
    unsigned uV = (unsigned)__cvta_generic_to_shared(Vb);
    unsigned uKps = (unsigned)__cvta_generic_to_shared(kps);

    int bh = blockIdx.y;
    int b = bh >> 3, h = bh & 7;
    int q0 = (gridDim.x - 1 - blockIdx.x) << 7;
    size_t tb = (size_t)bh * TT;
    int tid = threadIdx.x;
    int lane = tid & 31, warp = tid >> 5;
    int g = lane >> 2, tig = lane & 3;
    int r0loc = warp*16 + g, r1loc = r0loc + 8;
    int lra = ((lane >> 3) & 1) * 8 + (lane & 7);
    int lca = (lane >> 4) * 8;

    {
        const __half* qhg = qh + (tb + q0) * DD;
        for (int i = tid; i < 2048; i += 256) {
            int r = i >> 4, c = (i & 15) << 3;
            *(uint4*)&Qh[r*KSTR + c] = *(const uint4*)&qhg[r*DD + c];
        }
    }
    float hs  = hsc[h];
    float qp0 = qp[tb + q0 + r0loc];
    float qp1 = qp[tb + q0 + r1loc];
    int ntiles = (q0 >> 6) + 2;

    auto prefetch = [&](int st, int n0) {
        const __half* khg = kh + (tb + n0) * DD;
        const __half* klg = kl + (tb + n0) * DD;
        for (int i = tid; i < 1024; i += 256) {
            int r = i >> 4, c = (i & 15) << 3;
            CP16(uK + (unsigned)(((st*128 + r)*KSTR + c) * 2),      khg + r*DD + c);
            CP16(uK + (unsigned)(((st*128 + 64 + r)*KSTR + c) * 2), klg + r*DD + c);
        }
        const __half* vhg = vth + (size_t)bh*DD*TT + n0;
        for (int i = tid; i < 1024; i += 256) {
            int d = i >> 3, c = (i & 7) << 3;
            CP16(uV + (unsigned)(((st*128 + d)*VSTR + c) * 2), vhg + (size_t)d*TT + c);
        }
        if (tid < 64) CP4(uKps + (unsigned)((st*64 + tid) * 4), kp + tb + n0 + tid);
    };

    float O[16][4], Og[16][4];
    #pragma unroll
    for (int i = 0; i < 16; i++)
        #pragma unroll
        for (int j = 0; j < 4; j++) { O[i][j] = 0.f; Og[i][j] = 0.f; }
    float l0 = 0.f, l1 = 0.f, lg0 = 0.f, lg1 = 0.f;

    prefetch(0, 0);
    CP_COMMIT();
    for (int it = 0; it < ntiles; it++) {
        int st = it & 1;
        int n0 = it << 6;
        if (it + 1 < ntiles) { prefetch(st ^ 1, (it + 1) << 6); CP_COMMIT(); CP_WAIT1(); }
        else                 { CP_WAIT0(); }
        __syncthreads();

        // ---- S = Q K^T (2-term fp16: qh x kh + qh x kl)
        float s[8][4];
        #pragma unroll
        for (int i = 0; i < 8; i++)
            #pragma unroll
            for (int j = 0; j < 4; j++) s[i][j] = 0.f;
        #pragma unroll
        for (int kk = 0; kk < 8; kk++) {
            int col = kk*16 + lca;
            unsigned qoff = (unsigned)(((warp*16 + lra)*KSTR + col) * 2);
            unsigned qa[4];
            ldsm_x4(qa, uQ + qoff);
            #pragma unroll
            for (int np = 0; np < 2; np++) {
                unsigned kh4[2][4], kl4[2][4];
                #pragma unroll
                for (int u = 0; u < 2; u++) {
                    int ng = np*2 + u;
                    unsigned koff = (unsigned)(((st*128 + ng*16 + lra)*KSTR + col) * 2);
                    ldsm_x4(kh4[u], uK + koff);
                    ldsm_x4(kl4[u], uK + koff + (unsigned)(64*KSTR*2));
                }
                #pragma unroll
                for (int u = 0; u < 2; u++)
                    #pragma unroll
                    for (int hf = 0; hf < 2; hf++)
                        mma_f16(s[(np*2+u)*2 + hf], qa, kh4[u][hf], kh4[u][2 + hf]);
                #pragma unroll
                for (int u = 0; u < 2; u++)
                    #pragma unroll
                    for (int hf = 0; hf < 2; hf++)
                        mma_f16(s[(np*2+u)*2 + hf], qa, kl4[u][hf], kl4[u][2 + hf]);
            }
        }

        int relq = q0 - n0;
        #pragma unroll
        for (int ni = 0; ni < 8; ni++) {
            #pragma unroll
            for (int j = 0; j < 4; j++) {
                int cl = ni*8 + 2*tig + (j & 1);
                int rl = (j < 2) ? r0loc : r1loc;
                bool ok = (cl - rl <= relq);
                float e = ok ? __expf(s[ni][j] * SCALE) : 0.f;
                s[ni][j] = e;
                if (j < 2) l0 += e; else l1 += e;
            }
        }

        const float* kpst = kps + st*64;
        #pragma unroll
        for (int kc = 0; kc < 4; kc++) {
            unsigned ph[4], gh[4];
            ph[0] = pack2(s[2*kc][0],   s[2*kc][1]);
            ph[1] = pack2(s[2*kc][2],   s[2*kc][3]);
            ph[2] = pack2(s[2*kc+1][0], s[2*kc+1][1]);
            ph[3] = pack2(s[2*kc+1][2], s[2*kc+1][3]);
            {
                int c0 = kc*16 + 2*tig;
                float k0v = kpst[c0],     k1v = kpst[c0 + 1];
                float k8v = kpst[c0 + 8], k9v = kpst[c0 + 9];
                float ge00 = (c0     - r0loc <= relq) ? __expf(qp0 * k0v) : 0.f;
                float ge01 = (c0 + 1 - r0loc <= relq) ? __expf(qp0 * k1v) : 0.f;
                float ge10 = (c0     - r1loc <= relq) ? __expf(qp1 * k0v) : 0.f;
                float ge11 = (c0 + 1 - r1loc <= relq) ? __expf(qp1 * k1v) : 0.f;
                float ge08 = (c0 + 8 - r0loc <= relq) ? __expf(qp0 * k8v) : 0.f;
                float ge09 = (c0 + 9 - r0loc <= relq) ? __expf(qp0 * k9v) : 0.f;
                float ge18 = (c0 + 8 - r1loc <= relq) ? __expf(qp1 * k8v) : 0.f;
                float ge19 = (c0 + 9 - r1loc <= relq) ? __expf(qp1 * k9v) : 0.f;
                lg0 += ge00 + ge01 + ge08 + ge09;
                lg1 += ge10 + ge11 + ge18 + ge19;
                gh[0] = pack2(ge00, ge01);
                gh[1] = pack2(ge10, ge11);
                gh[2] = pack2(ge08, ge09);
                gh[3] = pack2(ge18, ge19);
            }
            // PV: O 1-term (ph x vh), Og 1-term (gh x vh)
            #pragma unroll
            for (int ndg = 0; ndg < 8; ndg++) {
                unsigned voff = (unsigned)(((st*128 + ndg*16 + lra)*VSTR + kc*16 + lca) * 2);
                unsigned vh4[4];
                ldsm_x4(vh4, uV + voff);
                int nd0 = ndg*2, nd1 = ndg*2 + 1;
                mma_f16(O[nd0],  ph, vh4[0], vh4[2]);
                mma_f16(O[nd1],  ph, vh4[1], vh4[3]);
                mma_f16(Og[nd0], gh, vh4[0], vh4[2]);
                mma_f16(Og[nd1], gh, vh4[1], vh4[3]);
            }
        }
        __syncthreads();
    }

    #pragma unroll
    for (int o = 1; o <= 2; o <<= 1) {
        l0  += __shfl_xor_sync(0xffffffffu, l0,  o);
        l1  += __shfl_xor_sync(0xffffffffu, l1,  o);
        lg0 += __shfl_xor_sync(0xffffffffu, lg0, o);
        lg1 += __shfl_xor_sync(0xffffffffu, lg1, o);
    }
    float c1a = (1.f - hs) / l0, c2a = hs / lg0;
    float c1b = (1.f - hs) / l1, c2b = hs / lg1;

    // epilogue: fp16 plane for Wo GEMM
    size_t orow0 = (size_t)(b*TT + q0 + r0loc) * CC + h*DD;
    size_t orow1 = (size_t)(b*TT + q0 + r1loc) * CC + h*DD;
    #pragma unroll
    for (int nd = 0; nd < 16; nd++) {
        int d0 = nd*8 + 2*tig;
        float v0 = c1a*O[nd][0] + c2a*Og[nd][0];
        float v1 = c1a*O[nd][1] + c2a*Og[nd][1];
        *(unsigned*)&aoh[orow0 + d0] = pack2(v0, v1);
        v0 = c1b*O[nd][2] + c2b*Og[nd][2];
        v1 = c1b*O[nd][3] + c2b*Og[nd][3];
        *(unsigned*)&aoh[orow1 + d0] = pack2(v0, v1);
    }
}

// ---------------------------------------------------------------------------
// Launcher
// ---------------------------------------------------------------------------
extern "C" void kernel_launch(void* const* d_in, const int* in_sizes, int n_in,
                              void* d_out, int out_size)
{
    const float* x   = (const float*)d_in[0];
    const float* Wq  = (const float*)d_in[1];
    const float* Wk  = (const float*)d_in[2];
    const float* Wv  = (const float*)d_in[3];
    const float* Wo  = (const float*)d_in[4];
    const float* lng = (const float*)d_in[5];
    const float* lnb = (const float*)d_in[6];
    const float* hsc = (const float*)d_in[7];
    const float* hdr = (const float*)d_in[8];
    float* out = (float*)d_out;

    unsigned char* base = nullptr;
    cudaGetSymbolAddress((void**)&base, g_scratch);
    __half* xnh = (__half*)(base + OFF_XNH);
    __half* wh  = (__half*)(base + OFF_WH);
    __half* wl  = (__half*)(base + OFF_WL);
    float* qf = (float*)(base + OFF_QF);
    float* kf = (float*)(base + OFF_KF);
    __half* qhp = (__half*)(base + OFF_QH);
    __half* khp = (__half*)(base + OFF_KH);
    __half* klp = (__half*)(base + OFF_KL);
    __half* vth = (__half*)(base + OFF_VTH);
    __half* aoh = (__half*)(base + OFF_AOH);
    float* gqp = (float*)(base + OFF_QP);
    float* gkp = (float*)(base + OFF_KP);
    float2* cst = (float2*)(base + OFF_CS);

    cudaFuncSetAttribute(gemm2<0>,
                         cudaFuncAttributeMaxDynamicSharedMemorySize, GEMM_SMEM);
    cudaFuncSetAttribute(gemm2<1>,
                         cudaFuncAttributeMaxDynamicSharedMemorySize, GEMM_SMEM);
    cudaFuncSetAttribute(attn_mma,
                         cudaFuncAttributeMaxDynamicSharedMemorySize, ATTN_SMEM);

    rope_tab<<<TT, 64>>>(cst);
    ln_split<<<NTOK, 256>>>(x, lng, lnb, xnh);
    wsplit<<<4096, 256>>>(Wq, Wk, Wv, Wo, wh, wl);

    gemm2<0><<<dim3(24, NTOK/128), 256, GEMM_SMEM>>>(
        xnh, wh, wl, nullptr, qf, kf, vth);

    rope_kernel<<<BH*TT, 128>>>(qf, kf, hdr, cst, qhp, khp, klp, gqp, gkp);

    attn_mma<<<dim3(TT/128, BH), 256, ATTN_SMEM>>>(qhp, khp, klp, vth,
                                                   gqp, gkp, hsc, aoh);

    gemm2<1><<<dim3(8, NTOK/128), 256, GEMM_SMEM>>>(
        aoh, wh + 3*WPL, wl + 3*WPL, x, out, nullptr, nullptr);
}